// round 14
// baseline (speedup 1.0000x reference)
#include <cuda_runtime.h>
#include <cuda_bf16.h>
#include <math.h>
#include <stdint.h>
#include <stddef.h>

// Problem constants
#define NN_ 32768
#define EE_ 524288
#define CC_ 256
#define HH_ 8
#define BB_ 128
#define NCLS_ 10
#define PER_ 256
#define HD_ 32
#define EPS_ 1e-5f

// ---------------- scratch (static device globals; no allocation) ----------------
__device__ float g_out3[NN_ * CC_];     // out + ff (pre-BN3, fp32 for pool)
__device__ float g_dinv[NN_];
__device__ float g_sum[3 * CC_];
__device__ float g_sq[3 * CC_];
// bf16 operands / intermediates
__device__ __nv_bfloat16 g_h_bf[NN_ * CC_];
__device__ __nv_bfloat16 g_qkv_bf[NN_ * 3 * CC_];
__device__ __nv_bfloat16 g_x_bf[NN_ * CC_];
__device__ __nv_bfloat16 g_attn_bf[NN_ * CC_];
__device__ __nv_bfloat16 g_h1_bf[NN_ * CC_];
__device__ __nv_bfloat16 g_h2_bf[NN_ * CC_];
__device__ __nv_bfloat16 g_out_bf[NN_ * CC_];
__device__ __nv_bfloat16 g_ff1_bf[NN_ * 2 * CC_];
__device__ __nv_bfloat16 g_WcT_bf[CC_ * CC_];
__device__ __nv_bfloat16 g_W1T_bf[2 * CC_ * CC_];
__device__ __nv_bfloat16 g_W2T_bf[CC_ * 2 * CC_];
__device__ __nv_bfloat16 g_ipw_bf[3 * CC_ * CC_];
__device__ __nv_bfloat16 g_opw_bf[CC_ * CC_];
// CSR for gather
__device__ int g_cnt[NN_];
__device__ int g_off[NN_ + 1];
__device__ int g_cur[NN_];
__device__ int g_src[EE_];

// ---------------- helpers ----------------
__device__ __forceinline__ uint32_t smem_u32(const void* p) {
    uint32_t a;
    asm("{ .reg .u64 t; cvta.to.shared.u64 t, %1; cvt.u32.u64 %0, t; }" : "=r"(a) : "l"(p));
    return a;
}
#define CP_COMMIT() asm volatile("cp.async.commit_group;" ::: "memory")
#define CP_WAIT1() asm volatile("cp.async.wait_group 1;" ::: "memory")
#define CP_WAIT0() asm volatile("cp.async.wait_group 0;" ::: "memory")

__device__ __forceinline__ uint32_t pk(float lo, float hi) {
    uint32_t r;
    asm("cvt.rn.bf16x2.f32 %0, %1, %2;" : "=r"(r) : "f"(hi), "f"(lo));
    return r;
}
__device__ __forceinline__ float2 upk(uint32_t w) {
    __nv_bfloat162 t = *(__nv_bfloat162*)&w;
    return __bfloat1622float2(t);
}
__device__ __forceinline__ void mma16(float* c, const uint32_t* a, const uint32_t* b) {
    asm volatile("mma.sync.aligned.m16n8k16.row.col.f32.bf16.bf16.f32 "
        "{%0,%1,%2,%3}, {%4,%5,%6,%7}, {%8,%9}, {%0,%1,%2,%3};"
        : "+f"(c[0]), "+f"(c[1]), "+f"(c[2]), "+f"(c[3])
        : "r"(a[0]), "r"(a[1]), "r"(a[2]), "r"(a[3]), "r"(b[0]), "r"(b[1]));
}
__device__ __forceinline__ void ldsm4(uint32_t* r, uint32_t addr) {
    asm volatile("ldmatrix.sync.aligned.m8n8.x4.shared.b16 {%0,%1,%2,%3}, [%4];"
        : "=r"(r[0]), "=r"(r[1]), "=r"(r[2]), "=r"(r[3]) : "r"(addr));
}
__device__ __forceinline__ float fast_exp2(float z) {
    float fz = z + 12582912.0f;
    int n = __float_as_int(fz) - 0x4B400000;
    float f = z - (fz - 12582912.0f);
    float p = 0.0013333558f;
    p = fmaf(p, f, 0.0096181291f);
    p = fmaf(p, f, 0.0555041087f);
    p = fmaf(p, f, 0.2402265070f);
    p = fmaf(p, f, 0.6931471806f);
    p = fmaf(p, f, 1.0f);
    return p * __int_as_float((n + 127) << 23);
}
#define ATT_C (1.4426950408889634f * 0.17677669529663687f)
__device__ __forceinline__ float fast_exp_s(float s) { return fast_exp2(s * ATT_C); }

// ---------------- zero ----------------
__global__ void zero_kernel() {
    int i = blockIdx.x * blockDim.x + threadIdx.x;
    if (i < NN_) g_cnt[i] = 0;
    if (i < 3 * CC_) { g_sum[i] = 0.0f; g_sq[i] = 0.0f; }
}

// ---------------- prep ----------------
__device__ __forceinline__ void transpose_tile_bf(const float* __restrict__ in, __nv_bfloat16* __restrict__ out,
                                                  int R, int Cc, int bx, int by) {
    __shared__ float t[32][33];
    int tx = threadIdx.x & 31, ty = threadIdx.x >> 5;
    int x = bx * 32 + tx;
    #pragma unroll
    for (int i = 0; i < 32; i += 8) t[ty + i][tx] = in[(size_t)(by * 32 + ty + i) * Cc + x];
    __syncthreads();
    int xo = by * 32 + tx;
    #pragma unroll
    for (int i = 0; i < 32; i += 8)
        out[(size_t)(bx * 32 + ty + i) * R + xo] = __float2bfloat16(t[tx][ty + i]);
}

__device__ __forceinline__ void conv_range(const float* __restrict__ in, __nv_bfloat16* __restrict__ out,
                                           int blk, int tid) {
    int base = blk * 2048 + tid * 8;
    float4 v0 = *(const float4*)(in + base);
    float4 v1 = *(const float4*)(in + base + 4);
    uint32_t* o = (uint32_t*)(out + base);
    o[0] = pk(v0.x, v0.y); o[1] = pk(v0.z, v0.w);
    o[2] = pk(v1.x, v1.y); o[3] = pk(v1.z, v1.w);
}

__global__ void __launch_bounds__(256) prep_kernel(const float* __restrict__ W_conv,
                                                   const float* __restrict__ mlp_w1,
                                                   const float* __restrict__ mlp_w2,
                                                   const float* __restrict__ in_proj_w,
                                                   const float* __restrict__ out_proj_w,
                                                   const float* __restrict__ x,
                                                   const int* __restrict__ col) {
    int b = blockIdx.x;
    int tid = threadIdx.x;
    if (b < 64) {
        transpose_tile_bf(W_conv, g_WcT_bf, CC_, CC_, b & 7, b >> 3);
    } else if (b < 192) {
        int bb = b - 64;
        transpose_tile_bf(mlp_w1, g_W1T_bf, CC_, 2 * CC_, bb & 15, bb >> 4);
    } else if (b < 320) {
        int bb = b - 192;
        transpose_tile_bf(mlp_w2, g_W2T_bf, 2 * CC_, CC_, bb & 7, bb >> 3);
    } else if (b < 416) {
        conv_range(in_proj_w, g_ipw_bf, b - 320, tid);
    } else if (b < 448) {
        conv_range(out_proj_w, g_opw_bf, b - 416, tid);
    } else if (b < 4544) {
        conv_range(x, g_x_bf, b - 448, tid);
    } else {
        int e = (b - 4544) * 256 + tid;
        if (e < EE_) atomicAdd(&g_cnt[col[e]], 1);
    }
}

// ---------------- scan body (256 threads, runs inside EPI4 GEMM launch) ----------------
__device__ void scan_body() {
    __shared__ int sp[256];
    int t = threadIdx.x;
    int base = t * 128;
    int run = 0;
    for (int i = 0; i < 128; i++) run += g_cnt[base + i];
    sp[t] = run;
    __syncthreads();
    for (int d = 1; d < 256; d <<= 1) {
        int v = sp[t];
        int u = (t >= d) ? sp[t - d] : 0;
        __syncthreads();
        sp[t] = v + u;
        __syncthreads();
    }
    int o = (t > 0) ? sp[t - 1] : 0;
    for (int i = 0; i < 128; i++) {
        int cnt = g_cnt[base + i];
        g_off[base + i] = o;
        g_cur[base + i] = o;
        g_dinv[base + i] = rsqrtf((float)(cnt + 1));
        o += cnt;
    }
    if (t == 255) g_off[NN_] = EE_;
}

// ---------------- fill CSR ----------------
__global__ void fill_kernel(const int* __restrict__ row, const int* __restrict__ col) {
    int e = blockIdx.x * blockDim.x + threadIdx.x;
    if (e >= EE_) return;
    int c = col[e];
    int p = atomicAdd(&g_cur[c], 1);
    g_src[p] = row[e];
}

// ---------------- gather body ----------------
__device__ __forceinline__ void acc8(float* acc, float w, uint4 u) {
    float2 f0 = upk(u.x), f1 = upk(u.y), f2 = upk(u.z), f3 = upk(u.w);
    acc[0] = fmaf(w, f0.x, acc[0]); acc[1] = fmaf(w, f0.y, acc[1]);
    acc[2] = fmaf(w, f1.x, acc[2]); acc[3] = fmaf(w, f1.y, acc[3]);
    acc[4] = fmaf(w, f2.x, acc[4]); acc[5] = fmaf(w, f2.y, acc[5]);
    acc[6] = fmaf(w, f3.x, acc[6]); acc[7] = fmaf(w, f3.y, acc[7]);
}

__device__ void gather_node(int gw, int lane, const float* __restrict__ x,
                            const float* __restrict__ b_conv) {
    int beg = g_off[gw], end = g_off[gw + 1];
    float acc[8] = {0, 0, 0, 0, 0, 0, 0, 0};
    for (int e0 = beg; e0 < end; e0 += 32) {
        int nb = min(32, end - e0);
        int src = (e0 + lane < end) ? g_src[e0 + lane] : 0;
        int j = 0;
        for (; j + 4 <= nb; j += 4) {
            int r0 = __shfl_sync(0xFFFFFFFF, src, j);
            int r1 = __shfl_sync(0xFFFFFFFF, src, j + 1);
            int r2 = __shfl_sync(0xFFFFFFFF, src, j + 2);
            int r3 = __shfl_sync(0xFFFFFFFF, src, j + 3);
            float w0 = g_dinv[r0], w1 = g_dinv[r1], w2 = g_dinv[r2], w3 = g_dinv[r3];
            uint4 u0 = *((const uint4*)(g_h_bf + (size_t)r0 * CC_) + lane);
            uint4 u1 = *((const uint4*)(g_h_bf + (size_t)r1 * CC_) + lane);
            uint4 u2 = *((const uint4*)(g_h_bf + (size_t)r2 * CC_) + lane);
            uint4 u3 = *((const uint4*)(g_h_bf + (size_t)r3 * CC_) + lane);
            acc8(acc, w0, u0); acc8(acc, w1, u1); acc8(acc, w2, u2); acc8(acc, w3, u3);
        }
        for (; j < nb; j++) {
            int r = __shfl_sync(0xFFFFFFFF, src, j);
            float w = g_dinv[r];
            uint4 u = *((const uint4*)(g_h_bf + (size_t)r * CC_) + lane);
            acc8(acc, w, u);
        }
    }
    float dn = g_dinv[gw];
    float dn2 = dn * dn;
    float self[8] = {0, 0, 0, 0, 0, 0, 0, 0};
    uint4 us = *((const uint4*)(g_h_bf + (size_t)gw * CC_) + lane);
    acc8(self, 1.0f, us);
    const float4* xn = (const float4*)(x + (size_t)gw * CC_) + lane * 2;
    const float4* bc = (const float4*)b_conv + lane * 2;
    float4 x0 = xn[0], x1 = xn[1];
    float4 b0 = bc[0], b1 = bc[1];
    float4 o0, o1;
    o0.x = fmaf(dn, acc[0], fmaf(dn2, self[0], b0.x + x0.x));
    o0.y = fmaf(dn, acc[1], fmaf(dn2, self[1], b0.y + x0.y));
    o0.z = fmaf(dn, acc[2], fmaf(dn2, self[2], b0.z + x0.z));
    o0.w = fmaf(dn, acc[3], fmaf(dn2, self[3], b0.w + x0.w));
    o1.x = fmaf(dn, acc[4], fmaf(dn2, self[4], b1.x + x1.x));
    o1.y = fmaf(dn, acc[5], fmaf(dn2, self[5], b1.y + x1.y));
    o1.z = fmaf(dn, acc[6], fmaf(dn2, self[6], b1.z + x1.z));
    o1.w = fmaf(dn, acc[7], fmaf(dn2, self[7], b1.w + x1.w));
    uint4 ov;
    ov.x = pk(o0.x, o0.y); ov.y = pk(o0.z, o0.w);
    ov.z = pk(o1.x, o1.y); ov.w = pk(o1.z, o1.w);
    *((uint4*)(g_h1_bf + (size_t)gw * CC_) + lane) = ov;
}

// ---------------- bf16 GEMM: 128x128 tile, K-chunk 32, 3-stage pipeline, ldmatrix ----
// One __syncthreads per chunk: barrier at iter c proves all warps finished chunk c-1,
// so issuing chunk c+2 into buf (c+2)%3 == buf (c-1)%3 after the barrier is race-free.
#define CHUNK_B 10240
#define BUF_B (2 * CHUNK_B)
#define GS3 (3 * BUF_B + 1024)

__device__ __forceinline__ void ld_chunk_bf(uint32_t dst, const __nv_bfloat16* __restrict__ g,
                                            int ld, int row0, int k0, int tid) {
    #pragma unroll
    for (int i = 0; i < 2; i++) {
        int seg = i * 256 + tid;
        int r = seg >> 2, s = seg & 3;
        uint32_t d = dst + (uint32_t)(r * 80 + s * 16);
        const __nv_bfloat16* src = g + (size_t)(row0 + r) * ld + k0 + s * 8;
        asm volatile("cp.async.cg.shared.global [%0], [%1], 16;" :: "r"(d), "l"(src));
    }
}

template<int EPI, int STATS>
__global__ void __launch_bounds__(256, 2) gemm_mma(
    const __nv_bfloat16* __restrict__ A, const __nv_bfloat16* __restrict__ Bt,
    const __nv_bfloat16* __restrict__ Bt2,
    const float* __restrict__ bias, const float* __restrict__ resid,
    float* __restrict__ C, __nv_bfloat16* __restrict__ Cbf, __nv_bfloat16* __restrict__ C2bf,
    float* __restrict__ gsum, float* __restrict__ gsq, int Nn, int K)
{
    if (EPI == 4) {
        if (blockIdx.y == 256) {
            if (blockIdx.x == 0) scan_body();
            return;
        }
    }
    if (STATS == 2) {
        if (blockIdx.y >= 256) {
            int idxb = (blockIdx.y - 256) * gridDim.x + blockIdx.x;
            int r0 = idxb * 128;
            int cch = threadIdx.x;
            float s = 0.0f, q = 0.0f;
            #pragma unroll 4
            for (int r = 0; r < 128; r++) {
                float v = __bfloat162float(g_h1_bf[(size_t)(r0 + r) * CC_ + cch]);
                s += v; q += v * v;
            }
            atomicAdd(&g_sum[cch], s);
            atomicAdd(&g_sq[cch], q);
            return;
        }
    }

    extern __shared__ char smc[];
    uint32_t sb = smem_u32(smc);
    float* ssum = (float*)(smc + 3 * BUF_B);
    float* ssq  = ssum + 128;
    int tid = threadIdx.x;
    int wid = tid >> 5, lane = tid & 31;
    int grp = lane >> 2, qd = lane & 3;
    int wm = wid >> 1, wn = wid & 1;
    int row0 = blockIdx.y * 128, col0 = blockIdx.x * 128;

    if (STATS && tid < 256) ((float*)(smc + 3 * BUF_B))[tid] = 0.0f;

    const __nv_bfloat16* Bsrc = Bt;
    int bro = col0;
    if (EPI == 4 && col0 >= 256) { Bsrc = Bt2; bro = col0 - 256; }

    int lrow = lane & 15, lhalf = lane >> 4;
    uint32_t aaddr[2];
    #pragma unroll
    for (int mf = 0; mf < 2; mf++)
        aaddr[mf] = sb + (uint32_t)((wm * 32 + mf * 16 + lrow) * 80 + lhalf * 16);
    int brow = (lane & 7) + ((lane >> 4) << 3);
    int bhalf = (lane >> 3) & 1;
    uint32_t baddr[4];
    #pragma unroll
    for (int p = 0; p < 4; p++)
        baddr[p] = sb + CHUNK_B + (uint32_t)((wn * 64 + 16 * p + brow) * 80 + bhalf * 16);

    float acc[2][8][4];
    #pragma unroll
    for (int mf = 0; mf < 2; mf++)
        #pragma unroll
        for (int nf = 0; nf < 8; nf++)
            #pragma unroll
            for (int j = 0; j < 4; j++) acc[mf][nf][j] = 0.0f;

    int nch = K >> 5;
    ld_chunk_bf(sb, A, K, row0, 0, tid);
    ld_chunk_bf(sb + CHUNK_B, Bsrc, K, bro, 0, tid);
    CP_COMMIT();
    ld_chunk_bf(sb + BUF_B, A, K, row0, 32, tid);
    ld_chunk_bf(sb + BUF_B + CHUNK_B, Bsrc, K, bro, 32, tid);
    CP_COMMIT();

    int st = 0;
    for (int c = 0; c < nch; c++) {
        if (c == nch - 1) { CP_WAIT0(); } else { CP_WAIT1(); }
        __syncthreads();
        if (c + 2 < nch) {
            int s2 = st + 2; if (s2 >= 3) s2 -= 3;
            ld_chunk_bf(sb + (uint32_t)(s2 * BUF_B), A, K, row0, (c + 2) << 5, tid);
            ld_chunk_bf(sb + (uint32_t)(s2 * BUF_B) + CHUNK_B, Bsrc, K, bro, (c + 2) << 5, tid);
            CP_COMMIT();
        }
        uint32_t stoff = (uint32_t)(st * BUF_B);
        #pragma unroll
        for (int kk = 0; kk < 2; kk++) {
            uint32_t ko = stoff + kk * 32;
            uint32_t a[2][4], b[8][2];
            ldsm4(a[0], aaddr[0] + ko);
            ldsm4(a[1], aaddr[1] + ko);
            #pragma unroll
            for (int p = 0; p < 4; p++) {
                uint32_t t4[4];
                ldsm4(t4, baddr[p] + ko);
                b[2 * p][0] = t4[0]; b[2 * p][1] = t4[1];
                b[2 * p + 1][0] = t4[2]; b[2 * p + 1][1] = t4[3];
            }
            #pragma unroll
            for (int mf = 0; mf < 2; mf++)
                #pragma unroll
                for (int nf = 0; nf < 8; nf++)
                    mma16(acc[mf][nf], a[mf], b[nf]);
        }
        st++; if (st == 3) st = 0;
    }
    __syncthreads();

    #pragma unroll
    for (int nf = 0; nf < 8; nf++) {
        float sc0 = 0, sc1 = 0, qc0 = 0, qc1 = 0;
        #pragma unroll
        for (int mf = 0; mf < 2; mf++) {
            int r1 = row0 + wm * 32 + mf * 16 + grp;
            int cc = col0 + wn * 64 + nf * 8 + qd * 2;
            float2 v0 = make_float2(acc[mf][nf][0], acc[mf][nf][1]);
            float2 v1 = make_float2(acc[mf][nf][2], acc[mf][nf][3]);
            if (EPI == 2 || EPI == 5 || EPI == 6) {
                float b0 = bias[cc], b1 = bias[cc + 1];
                v0.x += b0; v0.y += b1; v1.x += b0; v1.y += b1;
            }
            if (EPI == 2) {
                v0.x = fmaxf(v0.x, 0.0f); v0.y = fmaxf(v0.y, 0.0f);
                v1.x = fmaxf(v1.x, 0.0f); v1.y = fmaxf(v1.y, 0.0f);
                *(uint32_t*)(Cbf + (size_t)r1 * Nn + cc) = pk(v0.x, v0.y);
                *(uint32_t*)(Cbf + (size_t)(r1 + 8) * Nn + cc) = pk(v1.x, v1.y);
            }
            if (EPI == 5) {
                float2 ra = *(const float2*)(resid + (size_t)r1 * Nn + cc);
                float2 rb = *(const float2*)(resid + (size_t)(r1 + 8) * Nn + cc);
                v0.x += ra.x; v0.y += ra.y; v1.x += rb.x; v1.y += rb.y;
                *(uint32_t*)(Cbf + (size_t)r1 * Nn + cc) = pk(v0.x, v0.y);
                *(uint32_t*)(Cbf + (size_t)(r1 + 8) * Nn + cc) = pk(v1.x, v1.y);
            }
            if (EPI == 6) {
                uint32_t ra = *(const uint32_t*)(C2bf + (size_t)r1 * Nn + cc);
                uint32_t rb = *(const uint32_t*)(C2bf + (size_t)(r1 + 8) * Nn + cc);
                float2 fa = upk(ra), fb = upk(rb);
                v0.x += fa.x; v0.y += fa.y; v1.x += fb.x; v1.y += fb.y;
                *(float2*)(C + (size_t)r1 * Nn + cc) = v0;
                *(float2*)(C + (size_t)(r1 + 8) * Nn + cc) = v1;
            }
            if (EPI == 4) {
                if (col0 < 256) {
                    *(uint32_t*)(Cbf + (size_t)r1 * CC_ + cc) = pk(v0.x, v0.y);
                    *(uint32_t*)(Cbf + (size_t)(r1 + 8) * CC_ + cc) = pk(v1.x, v1.y);
                } else {
                    int cq = cc - 256;
                    float b0 = bias[cq], b1 = bias[cq + 1];
                    v0.x += b0; v0.y += b1; v1.x += b0; v1.y += b1;
                    *(uint32_t*)(C2bf + (size_t)r1 * (3 * CC_) + cq) = pk(v0.x, v0.y);
                    *(uint32_t*)(C2bf + (size_t)(r1 + 8) * (3 * CC_) + cq) = pk(v1.x, v1.y);
                }
            }
            if (STATS) {
                sc0 += v0.x + v1.x; sc1 += v0.y + v1.y;
                qc0 += v0.x * v0.x + v1.x * v1.x;
                qc1 += v0.y * v0.y + v1.y * v1.y;
            }
        }
        if (STATS) {
            #pragma unroll
            for (int m = 4; m <= 16; m <<= 1) {
                sc0 += __shfl_xor_sync(0xFFFFFFFF, sc0, m);
                sc1 += __shfl_xor_sync(0xFFFFFFFF, sc1, m);
                qc0 += __shfl_xor_sync(0xFFFFFFFF, qc0, m);
                qc1 += __shfl_xor_sync(0xFFFFFFFF, qc1, m);
            }
            if (lane < 4) {
                int ci = wn * 64 + nf * 8 + qd * 2;
                atomicAdd(&ssum[ci], sc0); atomicAdd(&ssum[ci + 1], sc1);
                atomicAdd(&ssq[ci], qc0);  atomicAdd(&ssq[ci + 1], qc1);
            }
        }
    }
    if (STATS) {
        __syncthreads();
        if (tid < 128) {
            atomicAdd(&gsum[col0 + tid], ssum[tid]);
            atomicAdd(&gsq[col0 + tid], ssq[tid]);
        }
    }
}

// ---------------- fused attention (blocks <1024) + gather (blocks >=1024) ----------------
#define AT_VT_OFF 5120
#define AT_SMEM_BYTES ((5120 + 32 * 132) * 4)

__global__ void __launch_bounds__(256) attn_gather(const __nv_bfloat16* __restrict__ qkv,
                                                   __nv_bfloat16* __restrict__ outbf,
                                                   const float* __restrict__ x,
                                                   const float* __restrict__ b_conv) {
    int tid = threadIdx.x;
    if (blockIdx.x >= 1024) {
        int gw = (blockIdx.x - 1024) * 8 + (tid >> 5);
        gather_node(gw, tid & 31, x, b_conv);
        return;
    }
    extern __shared__ uint32_t smw[];
    uint32_t* Ks = smw;
    uint32_t* Vt = smw + AT_VT_OFF;
    const uint32_t* qw = (const uint32_t*)qkv;
    int wid = tid >> 5, lane = tid & 31;
    int grp = lane >> 2, qd = lane & 3;
    int bx = blockIdx.x;
    int b = bx >> 3, h = bx & 7;
    int base = b * PER_;
    int m0 = wid * 32;

    for (int i = tid; i < 4096; i += 256) {
        int key = i >> 4, w = i & 15;
        Ks[key * 20 + w] = qw[(size_t)(base + key) * 384 + 128 + h * 16 + w];
    }
    {
        __nv_bfloat16* VtB = (__nv_bfloat16*)Vt;
        for (int i = tid; i < 4096; i += 256) {
            int key = i >> 4, w = i & 15;
            uint32_t u = qw[(size_t)(base + key) * 384 + 256 + h * 16 + w];
            __nv_bfloat162 t = *(__nv_bfloat162*)&u;
            VtB[(2 * w) * 264 + key] = t.x;
            VtB[(2 * w + 1) * 264 + key] = t.y;
        }
    }
    uint32_t qf[2][2][4];
    #pragma unroll
    for (int mf = 0; mf < 2; mf++) {
        size_t r0 = (size_t)(base + m0 + mf * 16 + grp) * 384 + h * 16;
        size_t r1 = r0 + 8 * 384;
        #pragma unroll
        for (int kt = 0; kt < 2; kt++) {
            qf[mf][kt][0] = qw[r0 + kt * 8 + qd];
            qf[mf][kt][1] = qw[r1 + kt * 8 + qd];
            qf[mf][kt][2] = qw[r0 + kt * 8 + qd + 4];
            qf[mf][kt][3] = qw[r1 + kt * 8 + qd + 4];
        }
    }
    __syncthreads();

    float oacc[2][4][4];
    #pragma unroll
    for (int mf = 0; mf < 2; mf++)
        #pragma unroll
        for (int nf = 0; nf < 4; nf++)
            #pragma unroll
            for (int j = 0; j < 4; j++) oacc[mf][nf][j] = 0.0f;
    float den[2][2] = {{0.0f, 0.0f}, {0.0f, 0.0f}};

    for (int ct = 0; ct < 8; ct++) {
        float sx[2][4][4];
        #pragma unroll
        for (int mf = 0; mf < 2; mf++)
            #pragma unroll
            for (int nf = 0; nf < 4; nf++)
                #pragma unroll
                for (int j = 0; j < 4; j++) sx[mf][nf][j] = 0.0f;
        #pragma unroll
        for (int nf = 0; nf < 4; nf++) {
            const uint32_t* kr = Ks + (ct * 32 + nf * 8 + grp) * 20;
            #pragma unroll
            for (int kt = 0; kt < 2; kt++) {
                uint32_t bb[2];
                bb[0] = kr[kt * 8 + qd];
                bb[1] = kr[kt * 8 + qd + 4];
                mma16(sx[0][nf], qf[0][kt], bb);
                mma16(sx[1][nf], qf[1][kt], bb);
            }
        }
        #pragma unroll
        for (int mf = 0; mf < 2; mf++)
            #pragma unroll
            for (int nf = 0; nf < 4; nf++) {
                float w0 = fast_exp_s(sx[mf][nf][0]);
                float w1 = fast_exp_s(sx[mf][nf][1]);
                float w2 = fast_exp_s(sx[mf][nf][2]);
                float w3 = fast_exp_s(sx[mf][nf][3]);
                den[mf][0] += w0 + w1;
                den[mf][1] += w2 + w3;
                sx[mf][nf][0] = w0; sx[mf][nf][1] = w1;
                sx[mf][nf][2] = w2; sx[mf][nf][3] = w3;
            }
        #pragma unroll
        for (int kt = 0; kt < 2; kt++) {
            uint32_t pa[2][4];
            #pragma unroll
            for (int mf = 0; mf < 2; mf++) {
                pa[mf][0] = pk(sx[mf][2 * kt][0],     sx[mf][2 * kt][1]);
                pa[mf][1] = pk(sx[mf][2 * kt][2],     sx[mf][2 * kt][3]);
                pa[mf][2] = pk(sx[mf][2 * kt + 1][0], sx[mf][2 * kt + 1][1]);
                pa[mf][3] = pk(sx[mf][2 * kt + 1][2], sx[mf][2 * kt + 1][3]);
            }
            #pragma unroll
            for (int nf = 0; nf < 4; nf++) {
                const uint32_t* vr = Vt + (nf * 8 + grp) * 132 + ct * 16 + kt * 8;
                uint32_t bb[2];
                bb[0] = vr[qd];
                bb[1] = vr[qd + 4];
                mma16(oacc[0][nf], pa[0], bb);
                mma16(oacc[1][nf], pa[1], bb);
            }
        }
    }

    #pragma unroll
    for (int mf = 0; mf < 2; mf++)
        #pragma unroll
        for (int r = 0; r < 2; r++) {
            float d = den[mf][r];
            d += __shfl_xor_sync(0xFFFFFFFF, d, 1);
            d += __shfl_xor_sync(0xFFFFFFFF, d, 2);
            den[mf][r] = 1.0f / d;
        }
    #pragma unroll
    for (int mf = 0; mf < 2; mf++) {
        int r0 = base + m0 + mf * 16 + grp;
        #pragma unroll
        for (int nf = 0; nf < 4; nf++) {
            int colx = h * HD_ + nf * 8 + 2 * qd;
            *(uint32_t*)(outbf + (size_t)r0 * CC_ + colx) =
                pk(oacc[mf][nf][0] * den[mf][0], oacc[mf][nf][1] * den[mf][0]);
            *(uint32_t*)(outbf + (size_t)(r0 + 8) * CC_ + colx) =
                pk(oacc[mf][nf][2] * den[mf][1], oacc[mf][nf][3] * den[mf][1]);
        }
    }
}

// ---------------- combine: out = BN1(h1) + BN2(h2), bf16 in/out ----------------
__global__ void combine_kernel(const float* __restrict__ g1, const float* __restrict__ b1,
                               const float* __restrict__ g2, const float* __restrict__ b2) {
    int gid = blockIdx.x * blockDim.x + threadIdx.x;
    int idx = gid * 2;
    if (idx >= NN_ * CC_) return;
    int c = idx & 255;
    const float invN = 1.0f / (float)NN_;
    float m1a = g_sum[c] * invN, m1b = g_sum[c + 1] * invN;
    float v1a = g_sq[c] * invN - m1a * m1a, v1b = g_sq[c + 1] * invN - m1b * m1b;
    float s1a = g1[c] * rsqrtf(v1a + EPS_), s1b = g1[c + 1] * rsqrtf(v1b + EPS_);
    float m2a = g_sum[CC_ + c] * invN, m2b = g_sum[CC_ + c + 1] * invN;
    float v2a = g_sq[CC_ + c] * invN - m2a * m2a, v2b = g_sq[CC_ + c + 1] * invN - m2b * m2b;
    float s2a = g2[c] * rsqrtf(v2a + EPS_), s2b = g2[c + 1] * rsqrtf(v2b + EPS_);
    float2 h1v = upk(*(const uint32_t*)(g_h1_bf + idx));
    float2 h2v = upk(*(const uint32_t*)(g_h2_bf + idx));
    float ya = (h1v.x - m1a) * s1a + b1[c]     + (h2v.x - m2a) * s2a + b2[c];
    float yb = (h1v.y - m1b) * s1b + b1[c + 1] + (h2v.y - m2b) * s2b + b2[c + 1];
    *(uint32_t*)(g_out_bf + idx) = pk(ya, yb);
}

// ---------------- fused pool + head ----------------
__global__ void pool_head_kernel(const float* __restrict__ g3, const float* __restrict__ b3,
                                 const float* __restrict__ fc_w, const float* __restrict__ fc_b,
                                 float* __restrict__ out) {
    int g = blockIdx.x;
    int c = threadIdx.x;
    __shared__ float pr[CC_];
    __shared__ float lo[NCLS_];
    __shared__ float red[2];
    const float invN = 1.0f / (float)NN_;
    float m3 = g_sum[2 * CC_ + c] * invN;
    float v3 = g_sq[2 * CC_ + c] * invN - m3 * m3;
    float s3 = g3[c] * rsqrtf(v3 + EPS_);
    float sh = b3[c] - m3 * s3;
    float mx = -INFINITY;
    #pragma unroll 4
    for (int p = 0; p < PER_; p++) {
        float v = g_out3[(size_t)(g * PER_ + p) * CC_ + c];
        mx = fmaxf(mx, v * s3 + sh);
    }
    pr[c] = mx;
    __syncthreads();
    if (c < NCLS_) {
        float s = fc_b[c];
        for (int k = 0; k < CC_; k++) s += pr[k] * fc_w[k * NCLS_ + c];
        lo[c] = s;
    }
    __syncthreads();
    if (c == 0) {
        float m = -INFINITY;
        for (int j = 0; j < NCLS_; j++) m = fmaxf(m, lo[j]);
        float se = 0.0f;
        for (int j = 0; j < NCLS_; j++) se += __expf(lo[j] - m);
        red[0] = m;
        red[1] = logf(se);
    }
    __syncthreads();
    if (c < NCLS_) out[g * NCLS_ + c] = lo[c] - red[0] - red[1];
}

// ---------------- launch ----------------
extern "C" void kernel_launch(void* const* d_in, const int* in_sizes, int n_in,
                              void* d_out, int out_size) {
    const float* x          = (const float*)d_in[0];
    const float* W_conv     = (const float*)d_in[1];
    const float* b_conv     = (const float*)d_in[2];
    const float* bn1_g      = (const float*)d_in[3];
    const float* bn1_b      = (const float*)d_in[4];
    const float* in_proj_w  = (const float*)d_in[5];
    const float* in_proj_b  = (const float*)d_in[6];
    const float* out_proj_w = (const float*)d_in[7];
    const float* out_proj_b = (const float*)d_in[8];
    const float* bn2_g      = (const float*)d_in[9];
    const float* bn2_b      = (const float*)d_in[10];
    const float* mlp_w1     = (const float*)d_in[11];
    const float* mlp_b1     = (const float*)d_in[12];
    const float* mlp_w2     = (const float*)d_in[13];
    const float* mlp_b2     = (const float*)d_in[14];
    const float* bn3_g      = (const float*)d_in[15];
    const float* bn3_b      = (const float*)d_in[16];
    const float* fc_w       = (const float*)d_in[17];
    const float* fc_b       = (const float*)d_in[18];
    const int*   edge_index = (const int*)d_in[19];
    float* out = (float*)d_out;

    const int* row = edge_index;
    const int* col = edge_index + EE_;

    cudaFuncSetAttribute(attn_gather, cudaFuncAttributeMaxDynamicSharedMemorySize, AT_SMEM_BYTES);
    cudaFuncSetAttribute(gemm_mma<4, 0>, cudaFuncAttributeMaxDynamicSharedMemorySize, GS3);
    cudaFuncSetAttribute(gemm_mma<5, 2>, cudaFuncAttributeMaxDynamicSharedMemorySize, GS3);
    cudaFuncSetAttribute(gemm_mma<2, 0>, cudaFuncAttributeMaxDynamicSharedMemorySize, GS3);
    cudaFuncSetAttribute(gemm_mma<6, 1>, cudaFuncAttributeMaxDynamicSharedMemorySize, GS3);

    float* out3_p; cudaGetSymbolAddress((void**)&out3_p, g_out3);
    float* sum_p;  cudaGetSymbolAddress((void**)&sum_p,  g_sum);
    float* sq_p;   cudaGetSymbolAddress((void**)&sq_p,   g_sq);
    __nv_bfloat16 *hbf_p, *qkvbf_p, *xbf_p, *attnbf_p, *h2bf_p, *outbf_p, *ff1bf_p;
    __nv_bfloat16 *WcT_p, *W1T_p, *W2T_p, *ipw_p, *opw_p;
    cudaGetSymbolAddress((void**)&hbf_p,    g_h_bf);
    cudaGetSymbolAddress((void**)&qkvbf_p,  g_qkv_bf);
    cudaGetSymbolAddress((void**)&xbf_p,    g_x_bf);
    cudaGetSymbolAddress((void**)&attnbf_p, g_attn_bf);
    cudaGetSymbolAddress((void**)&h2bf_p,   g_h2_bf);
    cudaGetSymbolAddress((void**)&outbf_p,  g_out_bf);
    cudaGetSymbolAddress((void**)&ff1bf_p,  g_ff1_bf);
    cudaGetSymbolAddress((void**)&WcT_p,    g_WcT_bf);
    cudaGetSymbolAddress((void**)&W1T_p,    g_W1T_bf);
    cudaGetSymbolAddress((void**)&W2T_p,    g_W2T_bf);
    cudaGetSymbolAddress((void**)&ipw_p,    g_ipw_bf);
    cudaGetSymbolAddress((void**)&opw_p,    g_opw_bf);

    // A: zero, prep
    zero_kernel<<<NN_ / 256, 256>>>();
    prep_kernel<<<4544 + EE_ / 256, 256>>>(W_conv, mlp_w1, mlp_w2, in_proj_w, out_proj_w, x, col);

    // B: fused h|qkv GEMM + scan block
    gemm_mma<4, 0><<<dim3(8, 257), 256, GS3>>>(xbf_p, WcT_p, ipw_p, in_proj_b, nullptr,
                                               nullptr, hbf_p, qkvbf_p, nullptr, nullptr, 0, CC_);
    // C: fill CSR
    fill_kernel<<<EE_ / 256, 256>>>(row, col);

    // D: attention + gather
    attn_gather<<<1024 + NN_ / 8, 256, AT_SMEM_BYTES>>>(qkvbf_p, attnbf_p, x, b_conv);

    // E: out_proj (+stats h2) + stats(h1) blocks
    gemm_mma<5, 2><<<dim3(2, 384), 256, GS3>>>(attnbf_p, opw_p, nullptr, out_proj_b, x,
                                               nullptr, h2bf_p, nullptr, sum_p + CC_, sq_p + CC_, CC_, CC_);
    // F: combine
    combine_kernel<<<NN_ * CC_ / 512, 256>>>(bn1_g, bn1_b, bn2_g, bn2_b);
    // G: ffn1
    gemm_mma<2, 0><<<dim3(4, 256), 256, GS3>>>(outbf_p, W1T_p, nullptr, mlp_b1, nullptr,
                                               nullptr, ff1bf_p, nullptr, nullptr, nullptr, 2 * CC_, CC_);
    // H: ffn2
    gemm_mma<6, 1><<<dim3(2, 256), 256, GS3>>>(ff1bf_p, W2T_p, nullptr, mlp_b2, nullptr,
                                               out3_p, nullptr, outbf_p, sum_p + 2 * CC_, sq_p + 2 * CC_, CC_, 2 * CC_);
    // I: pool + head
    pool_head_kernel<<<BB_, CC_>>>(bn3_g, bn3_b, fc_w, fc_b, out);
}

// round 15
// speedup vs baseline: 1.0303x; 1.0303x over previous
#include <cuda_runtime.h>
#include <cuda_bf16.h>
#include <math.h>
#include <stdint.h>
#include <stddef.h>

// Problem constants
#define NN_ 32768
#define EE_ 524288
#define CC_ 256
#define HH_ 8
#define BB_ 128
#define NCLS_ 10
#define PER_ 256
#define HD_ 32
#define EPS_ 1e-5f

// ---------------- scratch (static device globals; no allocation) ----------------
__device__ float g_dinv[NN_];
__device__ float g_sum[3 * CC_];
__device__ float g_sq[3 * CC_];
__device__ uint32_t g_mx[BB_ * CC_];   // per-(graph,channel) max of pre-BN3 value (encoded)
__device__ uint32_t g_mn[BB_ * CC_];   // per-(graph,channel) min (encoded)
// bf16 operands / intermediates
__device__ __nv_bfloat16 g_h_bf[NN_ * CC_];
__device__ __nv_bfloat16 g_qkv_bf[NN_ * 3 * CC_];
__device__ __nv_bfloat16 g_x_bf[NN_ * CC_];
__device__ __nv_bfloat16 g_attn_bf[NN_ * CC_];
__device__ __nv_bfloat16 g_h1_bf[NN_ * CC_];
__device__ __nv_bfloat16 g_h2_bf[NN_ * CC_];
__device__ __nv_bfloat16 g_out_bf[NN_ * CC_];
__device__ __nv_bfloat16 g_ff1_bf[NN_ * 2 * CC_];
__device__ __nv_bfloat16 g_WcT_bf[CC_ * CC_];
__device__ __nv_bfloat16 g_W1T_bf[2 * CC_ * CC_];
__device__ __nv_bfloat16 g_W2T_bf[CC_ * 2 * CC_];
__device__ __nv_bfloat16 g_ipw_bf[3 * CC_ * CC_];
__device__ __nv_bfloat16 g_opw_bf[CC_ * CC_];
// CSR for gather
__device__ int g_cnt[NN_];
__device__ int g_off[NN_ + 1];
__device__ int g_cur[NN_];
__device__ int g_src[EE_];

// ---------------- helpers ----------------
__device__ __forceinline__ uint32_t smem_u32(const void* p) {
    uint32_t a;
    asm("{ .reg .u64 t; cvta.to.shared.u64 t, %1; cvt.u32.u64 %0, t; }" : "=r"(a) : "l"(p));
    return a;
}
#define CP_COMMIT() asm volatile("cp.async.commit_group;" ::: "memory")
#define CP_WAIT1() asm volatile("cp.async.wait_group 1;" ::: "memory")
#define CP_WAIT0() asm volatile("cp.async.wait_group 0;" ::: "memory")

__device__ __forceinline__ uint32_t pk(float lo, float hi) {
    uint32_t r;
    asm("cvt.rn.bf16x2.f32 %0, %1, %2;" : "=r"(r) : "f"(hi), "f"(lo));
    return r;
}
__device__ __forceinline__ float2 upk(uint32_t w) {
    __nv_bfloat162 t = *(__nv_bfloat162*)&w;
    return __bfloat1622float2(t);
}
// monotone float<->uint encoding for atomicMax/Min
__device__ __forceinline__ uint32_t fenc(float f) {
    uint32_t u = __float_as_uint(f);
    return (u & 0x80000000u) ? ~u : (u | 0x80000000u);
}
__device__ __forceinline__ float fdec(uint32_t e) {
    uint32_t u = (e & 0x80000000u) ? (e & 0x7FFFFFFFu) : ~e;
    return __uint_as_float(u);
}
__device__ __forceinline__ void mma16(float* c, const uint32_t* a, const uint32_t* b) {
    asm volatile("mma.sync.aligned.m16n8k16.row.col.f32.bf16.bf16.f32 "
        "{%0,%1,%2,%3}, {%4,%5,%6,%7}, {%8,%9}, {%0,%1,%2,%3};"
        : "+f"(c[0]), "+f"(c[1]), "+f"(c[2]), "+f"(c[3])
        : "r"(a[0]), "r"(a[1]), "r"(a[2]), "r"(a[3]), "r"(b[0]), "r"(b[1]));
}
__device__ __forceinline__ void ldsm4(uint32_t* r, uint32_t addr) {
    asm volatile("ldmatrix.sync.aligned.m8n8.x4.shared.b16 {%0,%1,%2,%3}, [%4];"
        : "=r"(r[0]), "=r"(r[1]), "=r"(r[2]), "=r"(r[3]) : "r"(addr));
}
__device__ __forceinline__ float fast_exp2(float z) {
    float fz = z + 12582912.0f;
    int n = __float_as_int(fz) - 0x4B400000;
    float f = z - (fz - 12582912.0f);
    float p = 0.0013333558f;
    p = fmaf(p, f, 0.0096181291f);
    p = fmaf(p, f, 0.0555041087f);
    p = fmaf(p, f, 0.2402265070f);
    p = fmaf(p, f, 0.6931471806f);
    p = fmaf(p, f, 1.0f);
    return p * __int_as_float((n + 127) << 23);
}
#define ATT_C (1.4426950408889634f * 0.17677669529663687f)
__device__ __forceinline__ float fast_exp_s(float s) { return fast_exp2(s * ATT_C); }

// ---------------- zero ----------------
__global__ void zero_kernel() {
    int i = blockIdx.x * blockDim.x + threadIdx.x;
    if (i < NN_) {
        g_cnt[i] = 0;
        g_mx[i] = 0u;            // below enc(-inf)
        g_mn[i] = 0xFFFFFFFFu;   // above enc(+inf)
    }
    if (i < 3 * CC_) { g_sum[i] = 0.0f; g_sq[i] = 0.0f; }
}

// ---------------- prep ----------------
__device__ __forceinline__ void transpose_tile_bf(const float* __restrict__ in, __nv_bfloat16* __restrict__ out,
                                                  int R, int Cc, int bx, int by) {
    __shared__ float t[32][33];
    int tx = threadIdx.x & 31, ty = threadIdx.x >> 5;
    int x = bx * 32 + tx;
    #pragma unroll
    for (int i = 0; i < 32; i += 8) t[ty + i][tx] = in[(size_t)(by * 32 + ty + i) * Cc + x];
    __syncthreads();
    int xo = by * 32 + tx;
    #pragma unroll
    for (int i = 0; i < 32; i += 8)
        out[(size_t)(bx * 32 + ty + i) * R + xo] = __float2bfloat16(t[tx][ty + i]);
}

__device__ __forceinline__ void conv_range(const float* __restrict__ in, __nv_bfloat16* __restrict__ out,
                                           int blk, int tid) {
    int base = blk * 2048 + tid * 8;
    float4 v0 = *(const float4*)(in + base);
    float4 v1 = *(const float4*)(in + base + 4);
    uint32_t* o = (uint32_t*)(out + base);
    o[0] = pk(v0.x, v0.y); o[1] = pk(v0.z, v0.w);
    o[2] = pk(v1.x, v1.y); o[3] = pk(v1.z, v1.w);
}

__global__ void __launch_bounds__(256) prep_kernel(const float* __restrict__ W_conv,
                                                   const float* __restrict__ mlp_w1,
                                                   const float* __restrict__ mlp_w2,
                                                   const float* __restrict__ in_proj_w,
                                                   const float* __restrict__ out_proj_w,
                                                   const float* __restrict__ x,
                                                   const int* __restrict__ col) {
    int b = blockIdx.x;
    int tid = threadIdx.x;
    if (b < 64) {
        transpose_tile_bf(W_conv, g_WcT_bf, CC_, CC_, b & 7, b >> 3);
    } else if (b < 192) {
        int bb = b - 64;
        transpose_tile_bf(mlp_w1, g_W1T_bf, CC_, 2 * CC_, bb & 15, bb >> 4);
    } else if (b < 320) {
        int bb = b - 192;
        transpose_tile_bf(mlp_w2, g_W2T_bf, 2 * CC_, CC_, bb & 7, bb >> 3);
    } else if (b < 416) {
        conv_range(in_proj_w, g_ipw_bf, b - 320, tid);
    } else if (b < 448) {
        conv_range(out_proj_w, g_opw_bf, b - 416, tid);
    } else if (b < 4544) {
        conv_range(x, g_x_bf, b - 448, tid);
    } else {
        int e = (b - 4544) * 256 + tid;
        if (e < EE_) atomicAdd(&g_cnt[col[e]], 1);
    }
}

// ---------------- scan body (256 threads, runs inside EPI4 GEMM launch) ----------------
__device__ void scan_body() {
    __shared__ int sp[256];
    int t = threadIdx.x;
    int base = t * 128;
    int run = 0;
    for (int i = 0; i < 128; i++) run += g_cnt[base + i];
    sp[t] = run;
    __syncthreads();
    for (int d = 1; d < 256; d <<= 1) {
        int v = sp[t];
        int u = (t >= d) ? sp[t - d] : 0;
        __syncthreads();
        sp[t] = v + u;
        __syncthreads();
    }
    int o = (t > 0) ? sp[t - 1] : 0;
    for (int i = 0; i < 128; i++) {
        int cnt = g_cnt[base + i];
        g_off[base + i] = o;
        g_cur[base + i] = o;
        g_dinv[base + i] = rsqrtf((float)(cnt + 1));
        o += cnt;
    }
    if (t == 255) g_off[NN_] = EE_;
}

// ---------------- fill CSR ----------------
__global__ void fill_kernel(const int* __restrict__ row, const int* __restrict__ col) {
    int e = blockIdx.x * blockDim.x + threadIdx.x;
    if (e >= EE_) return;
    int c = col[e];
    int p = atomicAdd(&g_cur[c], 1);
    g_src[p] = row[e];
}

// ---------------- gather body ----------------
__device__ __forceinline__ void acc8(float* acc, float w, uint4 u) {
    float2 f0 = upk(u.x), f1 = upk(u.y), f2 = upk(u.z), f3 = upk(u.w);
    acc[0] = fmaf(w, f0.x, acc[0]); acc[1] = fmaf(w, f0.y, acc[1]);
    acc[2] = fmaf(w, f1.x, acc[2]); acc[3] = fmaf(w, f1.y, acc[3]);
    acc[4] = fmaf(w, f2.x, acc[4]); acc[5] = fmaf(w, f2.y, acc[5]);
    acc[6] = fmaf(w, f3.x, acc[6]); acc[7] = fmaf(w, f3.y, acc[7]);
}

__device__ void gather_node(int gw, int lane, const float* __restrict__ x,
                            const float* __restrict__ b_conv) {
    int beg = g_off[gw], end = g_off[gw + 1];
    float acc[8] = {0, 0, 0, 0, 0, 0, 0, 0};
    for (int e0 = beg; e0 < end; e0 += 32) {
        int nb = min(32, end - e0);
        int src = (e0 + lane < end) ? g_src[e0 + lane] : 0;
        int j = 0;
        for (; j + 4 <= nb; j += 4) {
            int r0 = __shfl_sync(0xFFFFFFFF, src, j);
            int r1 = __shfl_sync(0xFFFFFFFF, src, j + 1);
            int r2 = __shfl_sync(0xFFFFFFFF, src, j + 2);
            int r3 = __shfl_sync(0xFFFFFFFF, src, j + 3);
            float w0 = g_dinv[r0], w1 = g_dinv[r1], w2 = g_dinv[r2], w3 = g_dinv[r3];
            uint4 u0 = *((const uint4*)(g_h_bf + (size_t)r0 * CC_) + lane);
            uint4 u1 = *((const uint4*)(g_h_bf + (size_t)r1 * CC_) + lane);
            uint4 u2 = *((const uint4*)(g_h_bf + (size_t)r2 * CC_) + lane);
            uint4 u3 = *((const uint4*)(g_h_bf + (size_t)r3 * CC_) + lane);
            acc8(acc, w0, u0); acc8(acc, w1, u1); acc8(acc, w2, u2); acc8(acc, w3, u3);
        }
        for (; j < nb; j++) {
            int r = __shfl_sync(0xFFFFFFFF, src, j);
            float w = g_dinv[r];
            uint4 u = *((const uint4*)(g_h_bf + (size_t)r * CC_) + lane);
            acc8(acc, w, u);
        }
    }
    float dn = g_dinv[gw];
    float dn2 = dn * dn;
    float self[8] = {0, 0, 0, 0, 0, 0, 0, 0};
    uint4 us = *((const uint4*)(g_h_bf + (size_t)gw * CC_) + lane);
    acc8(self, 1.0f, us);
    const float4* xn = (const float4*)(x + (size_t)gw * CC_) + lane * 2;
    const float4* bc = (const float4*)b_conv + lane * 2;
    float4 x0 = xn[0], x1 = xn[1];
    float4 b0 = bc[0], b1 = bc[1];
    float4 o0, o1;
    o0.x = fmaf(dn, acc[0], fmaf(dn2, self[0], b0.x + x0.x));
    o0.y = fmaf(dn, acc[1], fmaf(dn2, self[1], b0.y + x0.y));
    o0.z = fmaf(dn, acc[2], fmaf(dn2, self[2], b0.z + x0.z));
    o0.w = fmaf(dn, acc[3], fmaf(dn2, self[3], b0.w + x0.w));
    o1.x = fmaf(dn, acc[4], fmaf(dn2, self[4], b1.x + x1.x));
    o1.y = fmaf(dn, acc[5], fmaf(dn2, self[5], b1.y + x1.y));
    o1.z = fmaf(dn, acc[6], fmaf(dn2, self[6], b1.z + x1.z));
    o1.w = fmaf(dn, acc[7], fmaf(dn2, self[7], b1.w + x1.w));
    uint4 ov;
    ov.x = pk(o0.x, o0.y); ov.y = pk(o0.z, o0.w);
    ov.z = pk(o1.x, o1.y); ov.w = pk(o1.z, o1.w);
    *((uint4*)(g_h1_bf + (size_t)gw * CC_) + lane) = ov;
}

// ---------------- bf16 GEMM: 128x128 tile, K-chunk 32, 2-stage (R13-proven), ldmatrix ----
// EPI: 2 bias+relu->bf16 | 4 split h|qkv ->bf16 (+scan block) |
//      5 bias+fp32resid->bf16 | 6 bias+bf16resid-> per-graph max/min only (no store)
// STATS: 0 none | 1 epilogue col-stats | 2 epilogue col-stats + h1-stats blocks
#define CHUNK_B 10240
#define BUF_B (2 * CHUNK_B)
#define GS3 (2 * BUF_B + 2048)

__device__ __forceinline__ void ld_chunk_bf(uint32_t dst, const __nv_bfloat16* __restrict__ g,
                                            int ld, int row0, int k0, int tid) {
    #pragma unroll
    for (int i = 0; i < 2; i++) {
        int seg = i * 256 + tid;
        int r = seg >> 2, s = seg & 3;
        uint32_t d = dst + (uint32_t)(r * 80 + s * 16);
        const __nv_bfloat16* src = g + (size_t)(row0 + r) * ld + k0 + s * 8;
        asm volatile("cp.async.cg.shared.global [%0], [%1], 16;" :: "r"(d), "l"(src));
    }
}

template<int EPI, int STATS>
__global__ void __launch_bounds__(256, 2) gemm_mma(
    const __nv_bfloat16* __restrict__ A, const __nv_bfloat16* __restrict__ Bt,
    const __nv_bfloat16* __restrict__ Bt2,
    const float* __restrict__ bias, const float* __restrict__ resid,
    float* __restrict__ C, __nv_bfloat16* __restrict__ Cbf, __nv_bfloat16* __restrict__ C2bf,
    float* __restrict__ gsum, float* __restrict__ gsq, int Nn, int K)
{
    if (EPI == 4) {
        if (blockIdx.y == 256) {
            if (blockIdx.x == 0) scan_body();
            return;
        }
    }
    if (STATS == 2) {
        if (blockIdx.y >= 256) {
            int idxb = (blockIdx.y - 256) * gridDim.x + blockIdx.x;
            int r0 = idxb * 128;
            int cch = threadIdx.x;
            float s = 0.0f, q = 0.0f;
            #pragma unroll 4
            for (int r = 0; r < 128; r++) {
                float v = __bfloat162float(g_h1_bf[(size_t)(r0 + r) * CC_ + cch]);
                s += v; q += v * v;
            }
            atomicAdd(&g_sum[cch], s);
            atomicAdd(&g_sq[cch], q);
            return;
        }
    }

    extern __shared__ char smc[];
    uint32_t sb = smem_u32(smc);
    float* ssum = (float*)(smc + 2 * BUF_B);
    float* ssq  = ssum + 128;
    uint32_t* smx = (uint32_t*)(ssq + 128);
    uint32_t* smn = smx + 128;
    int tid = threadIdx.x;
    int wid = tid >> 5, lane = tid & 31;
    int grp = lane >> 2, qd = lane & 3;
    int wm = wid >> 1, wn = wid & 1;
    int row0 = blockIdx.y * 128, col0 = blockIdx.x * 128;

    if (STATS && tid < 256) ((float*)(smc + 2 * BUF_B))[tid] = 0.0f;
    if (EPI == 6 && tid < 128) { smx[tid] = 0u; smn[tid] = 0xFFFFFFFFu; }

    const __nv_bfloat16* Bsrc = Bt;
    int bro = col0;
    if (EPI == 4 && col0 >= 256) { Bsrc = Bt2; bro = col0 - 256; }

    int lrow = lane & 15, lhalf = lane >> 4;
    uint32_t aaddr[2];
    #pragma unroll
    for (int mf = 0; mf < 2; mf++)
        aaddr[mf] = sb + (uint32_t)((wm * 32 + mf * 16 + lrow) * 80 + lhalf * 16);
    int brow = (lane & 7) + ((lane >> 4) << 3);
    int bhalf = (lane >> 3) & 1;
    uint32_t baddr[4];
    #pragma unroll
    for (int p = 0; p < 4; p++)
        baddr[p] = sb + CHUNK_B + (uint32_t)((wn * 64 + 16 * p + brow) * 80 + bhalf * 16);

    float acc[2][8][4];
    #pragma unroll
    for (int mf = 0; mf < 2; mf++)
        #pragma unroll
        for (int nf = 0; nf < 8; nf++)
            #pragma unroll
            for (int j = 0; j < 4; j++) acc[mf][nf][j] = 0.0f;

    int nch = K >> 5;
    ld_chunk_bf(sb, A, K, row0, 0, tid);
    ld_chunk_bf(sb + CHUNK_B, Bsrc, K, bro, 0, tid);
    CP_COMMIT();

    for (int c = 0; c < nch; c++) {
        int s = c & 1;
        if (c + 1 < nch) {
            int s2 = s ^ 1;
            ld_chunk_bf(sb + (uint32_t)(s2 * BUF_B), A, K, row0, (c + 1) << 5, tid);
            ld_chunk_bf(sb + (uint32_t)(s2 * BUF_B) + CHUNK_B, Bsrc, K, bro, (c + 1) << 5, tid);
            CP_COMMIT();
            CP_WAIT1();
        } else {
            CP_WAIT0();
        }
        __syncthreads();
        uint32_t stoff = (uint32_t)(s * BUF_B);
        #pragma unroll
        for (int kk = 0; kk < 2; kk++) {
            uint32_t ko = stoff + kk * 32;
            uint32_t a[2][4], b[8][2];
            ldsm4(a[0], aaddr[0] + ko);
            ldsm4(a[1], aaddr[1] + ko);
            #pragma unroll
            for (int p = 0; p < 4; p++) {
                uint32_t t4[4];
                ldsm4(t4, baddr[p] + ko);
                b[2 * p][0] = t4[0]; b[2 * p][1] = t4[1];
                b[2 * p + 1][0] = t4[2]; b[2 * p + 1][1] = t4[3];
            }
            #pragma unroll
            for (int mf = 0; mf < 2; mf++)
                #pragma unroll
                for (int nf = 0; nf < 8; nf++)
                    mma16(acc[mf][nf], a[mf], b[nf]);
        }
        __syncthreads();
    }

    #pragma unroll
    for (int nf = 0; nf < 8; nf++) {
        float sc0 = 0, sc1 = 0, qc0 = 0, qc1 = 0;
        float mx0 = -INFINITY, mx1 = -INFINITY, mn0 = INFINITY, mn1 = INFINITY;
        #pragma unroll
        for (int mf = 0; mf < 2; mf++) {
            int r1 = row0 + wm * 32 + mf * 16 + grp;
            int cc = col0 + wn * 64 + nf * 8 + qd * 2;
            float2 v0 = make_float2(acc[mf][nf][0], acc[mf][nf][1]);
            float2 v1 = make_float2(acc[mf][nf][2], acc[mf][nf][3]);
            if (EPI == 2 || EPI == 5 || EPI == 6) {
                float b0 = bias[cc], b1 = bias[cc + 1];
                v0.x += b0; v0.y += b1; v1.x += b0; v1.y += b1;
            }
            if (EPI == 2) {
                v0.x = fmaxf(v0.x, 0.0f); v0.y = fmaxf(v0.y, 0.0f);
                v1.x = fmaxf(v1.x, 0.0f); v1.y = fmaxf(v1.y, 0.0f);
                *(uint32_t*)(Cbf + (size_t)r1 * Nn + cc) = pk(v0.x, v0.y);
                *(uint32_t*)(Cbf + (size_t)(r1 + 8) * Nn + cc) = pk(v1.x, v1.y);
            }
            if (EPI == 5) {
                float2 ra = *(const float2*)(resid + (size_t)r1 * Nn + cc);
                float2 rb = *(const float2*)(resid + (size_t)(r1 + 8) * Nn + cc);
                v0.x += ra.x; v0.y += ra.y; v1.x += rb.x; v1.y += rb.y;
                *(uint32_t*)(Cbf + (size_t)r1 * Nn + cc) = pk(v0.x, v0.y);
                *(uint32_t*)(Cbf + (size_t)(r1 + 8) * Nn + cc) = pk(v1.x, v1.y);
            }
            if (EPI == 6) {
                uint32_t ra = *(const uint32_t*)(C2bf + (size_t)r1 * Nn + cc);
                uint32_t rb = *(const uint32_t*)(C2bf + (size_t)(r1 + 8) * Nn + cc);
                float2 fa = upk(ra), fb = upk(rb);
                v0.x += fa.x; v0.y += fa.y; v1.x += fb.x; v1.y += fb.y;
                mx0 = fmaxf(mx0, fmaxf(v0.x, v1.x));
                mx1 = fmaxf(mx1, fmaxf(v0.y, v1.y));
                mn0 = fminf(mn0, fminf(v0.x, v1.x));
                mn1 = fminf(mn1, fminf(v0.y, v1.y));
            }
            if (EPI == 4) {
                if (col0 < 256) {
                    *(uint32_t*)(Cbf + (size_t)r1 * CC_ + cc) = pk(v0.x, v0.y);
                    *(uint32_t*)(Cbf + (size_t)(r1 + 8) * CC_ + cc) = pk(v1.x, v1.y);
                } else {
                    int cq = cc - 256;
                    float b0 = bias[cq], b1 = bias[cq + 1];
                    v0.x += b0; v0.y += b1; v1.x += b0; v1.y += b1;
                    *(uint32_t*)(C2bf + (size_t)r1 * (3 * CC_) + cq) = pk(v0.x, v0.y);
                    *(uint32_t*)(C2bf + (size_t)(r1 + 8) * (3 * CC_) + cq) = pk(v1.x, v1.y);
                }
            }
            if (STATS) {
                sc0 += v0.x + v1.x; sc1 += v0.y + v1.y;
                qc0 += v0.x * v0.x + v1.x * v1.x;
                qc1 += v0.y * v0.y + v1.y * v1.y;
            }
        }
        if (STATS) {
            #pragma unroll
            for (int m = 4; m <= 16; m <<= 1) {
                sc0 += __shfl_xor_sync(0xFFFFFFFF, sc0, m);
                sc1 += __shfl_xor_sync(0xFFFFFFFF, sc1, m);
                qc0 += __shfl_xor_sync(0xFFFFFFFF, qc0, m);
                qc1 += __shfl_xor_sync(0xFFFFFFFF, qc1, m);
            }
            if (lane < 4) {
                int ci = wn * 64 + nf * 8 + qd * 2;
                atomicAdd(&ssum[ci], sc0); atomicAdd(&ssum[ci + 1], sc1);
                atomicAdd(&ssq[ci], qc0);  atomicAdd(&ssq[ci + 1], qc1);
            }
        }
        if (EPI == 6) {
            #pragma unroll
            for (int m = 4; m <= 16; m <<= 1) {
                mx0 = fmaxf(mx0, __shfl_xor_sync(0xFFFFFFFF, mx0, m));
                mx1 = fmaxf(mx1, __shfl_xor_sync(0xFFFFFFFF, mx1, m));
                mn0 = fminf(mn0, __shfl_xor_sync(0xFFFFFFFF, mn0, m));
                mn1 = fminf(mn1, __shfl_xor_sync(0xFFFFFFFF, mn1, m));
            }
            if (lane < 4) {
                int ci = wn * 64 + nf * 8 + qd * 2;
                atomicMax(&smx[ci], fenc(mx0)); atomicMax(&smx[ci + 1], fenc(mx1));
                atomicMin(&smn[ci], fenc(mn0)); atomicMin(&smn[ci + 1], fenc(mn1));
            }
        }
    }
    if (STATS || EPI == 6) {
        __syncthreads();
        if (tid < 128) {
            if (STATS) {
                atomicAdd(&gsum[col0 + tid], ssum[tid]);
                atomicAdd(&gsq[col0 + tid], ssq[tid]);
            }
            if (EPI == 6) {
                int graph = row0 >> 8;
                atomicMax(&g_mx[graph * CC_ + col0 + tid], smx[tid]);
                atomicMin(&g_mn[graph * CC_ + col0 + tid], smn[tid]);
            }
        }
    }
}

// ---------------- fused attention (blocks <1024) + gather (blocks >=1024) ----------------
#define AT_VT_OFF 5120
#define AT_SMEM_BYTES ((5120 + 32 * 132) * 4)

__global__ void __launch_bounds__(256) attn_gather(const __nv_bfloat16* __restrict__ qkv,
                                                   __nv_bfloat16* __restrict__ outbf,
                                                   const float* __restrict__ x,
                                                   const float* __restrict__ b_conv) {
    int tid = threadIdx.x;
    if (blockIdx.x >= 1024) {
        int gw = (blockIdx.x - 1024) * 8 + (tid >> 5);
        gather_node(gw, tid & 31, x, b_conv);
        return;
    }
    extern __shared__ uint32_t smw[];
    uint32_t* Ks = smw;
    uint32_t* Vt = smw + AT_VT_OFF;
    const uint32_t* qw = (const uint32_t*)qkv;
    int wid = tid >> 5, lane = tid & 31;
    int grp = lane >> 2, qd = lane & 3;
    int bx = blockIdx.x;
    int b = bx >> 3, h = bx & 7;
    int base = b * PER_;
    int m0 = wid * 32;

    for (int i = tid; i < 4096; i += 256) {
        int key = i >> 4, w = i & 15;
        Ks[key * 20 + w] = qw[(size_t)(base + key) * 384 + 128 + h * 16 + w];
    }
    {
        __nv_bfloat16* VtB = (__nv_bfloat16*)Vt;
        for (int i = tid; i < 4096; i += 256) {
            int key = i >> 4, w = i & 15;
            uint32_t u = qw[(size_t)(base + key) * 384 + 256 + h * 16 + w];
            __nv_bfloat162 t = *(__nv_bfloat162*)&u;
            VtB[(2 * w) * 264 + key] = t.x;
            VtB[(2 * w + 1) * 264 + key] = t.y;
        }
    }
    uint32_t qf[2][2][4];
    #pragma unroll
    for (int mf = 0; mf < 2; mf++) {
        size_t r0 = (size_t)(base + m0 + mf * 16 + grp) * 384 + h * 16;
        size_t r1 = r0 + 8 * 384;
        #pragma unroll
        for (int kt = 0; kt < 2; kt++) {
            qf[mf][kt][0] = qw[r0 + kt * 8 + qd];
            qf[mf][kt][1] = qw[r1 + kt * 8 + qd];
            qf[mf][kt][2] = qw[r0 + kt * 8 + qd + 4];
            qf[mf][kt][3] = qw[r1 + kt * 8 + qd + 4];
        }
    }
    __syncthreads();

    float oacc[2][4][4];
    #pragma unroll
    for (int mf = 0; mf < 2; mf++)
        #pragma unroll
        for (int nf = 0; nf < 4; nf++)
            #pragma unroll
            for (int j = 0; j < 4; j++) oacc[mf][nf][j] = 0.0f;
    float den[2][2] = {{0.0f, 0.0f}, {0.0f, 0.0f}};

    for (int ct = 0; ct < 8; ct++) {
        float sx[2][4][4];
        #pragma unroll
        for (int mf = 0; mf < 2; mf++)
            #pragma unroll
            for (int nf = 0; nf < 4; nf++)
                #pragma unroll
                for (int j = 0; j < 4; j++) sx[mf][nf][j] = 0.0f;
        #pragma unroll
        for (int nf = 0; nf < 4; nf++) {
            const uint32_t* kr = Ks + (ct * 32 + nf * 8 + grp) * 20;
            #pragma unroll
            for (int kt = 0; kt < 2; kt++) {
                uint32_t bb[2];
                bb[0] = kr[kt * 8 + qd];
                bb[1] = kr[kt * 8 + qd + 4];
                mma16(sx[0][nf], qf[0][kt], bb);
                mma16(sx[1][nf], qf[1][kt], bb);
            }
        }
        #pragma unroll
        for (int mf = 0; mf < 2; mf++)
            #pragma unroll
            for (int nf = 0; nf < 4; nf++) {
                float w0 = fast_exp_s(sx[mf][nf][0]);
                float w1 = fast_exp_s(sx[mf][nf][1]);
                float w2 = fast_exp_s(sx[mf][nf][2]);
                float w3 = fast_exp_s(sx[mf][nf][3]);
                den[mf][0] += w0 + w1;
                den[mf][1] += w2 + w3;
                sx[mf][nf][0] = w0; sx[mf][nf][1] = w1;
                sx[mf][nf][2] = w2; sx[mf][nf][3] = w3;
            }
        #pragma unroll
        for (int kt = 0; kt < 2; kt++) {
            uint32_t pa[2][4];
            #pragma unroll
            for (int mf = 0; mf < 2; mf++) {
                pa[mf][0] = pk(sx[mf][2 * kt][0],     sx[mf][2 * kt][1]);
                pa[mf][1] = pk(sx[mf][2 * kt][2],     sx[mf][2 * kt][3]);
                pa[mf][2] = pk(sx[mf][2 * kt + 1][0], sx[mf][2 * kt + 1][1]);
                pa[mf][3] = pk(sx[mf][2 * kt + 1][2], sx[mf][2 * kt + 1][3]);
            }
            #pragma unroll
            for (int nf = 0; nf < 4; nf++) {
                const uint32_t* vr = Vt + (nf * 8 + grp) * 132 + ct * 16 + kt * 8;
                uint32_t bb[2];
                bb[0] = vr[qd];
                bb[1] = vr[qd + 4];
                mma16(oacc[0][nf], pa[0], bb);
                mma16(oacc[1][nf], pa[1], bb);
            }
        }
    }

    #pragma unroll
    for (int mf = 0; mf < 2; mf++)
        #pragma unroll
        for (int r = 0; r < 2; r++) {
            float d = den[mf][r];
            d += __shfl_xor_sync(0xFFFFFFFF, d, 1);
            d += __shfl_xor_sync(0xFFFFFFFF, d, 2);
            den[mf][r] = 1.0f / d;
        }
    #pragma unroll
    for (int mf = 0; mf < 2; mf++) {
        int r0 = base + m0 + mf * 16 + grp;
        #pragma unroll
        for (int nf = 0; nf < 4; nf++) {
            int colx = h * HD_ + nf * 8 + 2 * qd;
            *(uint32_t*)(outbf + (size_t)r0 * CC_ + colx) =
                pk(oacc[mf][nf][0] * den[mf][0], oacc[mf][nf][1] * den[mf][0]);
            *(uint32_t*)(outbf + (size_t)(r0 + 8) * CC_ + colx) =
                pk(oacc[mf][nf][2] * den[mf][1], oacc[mf][nf][3] * den[mf][1]);
        }
    }
}

// ---------------- combine: out = BN1(h1) + BN2(h2), bf16 in/out ----------------
__global__ void combine_kernel(const float* __restrict__ g1, const float* __restrict__ b1,
                               const float* __restrict__ g2, const float* __restrict__ b2) {
    int gid = blockIdx.x * blockDim.x + threadIdx.x;
    int idx = gid * 2;
    if (idx >= NN_ * CC_) return;
    int c = idx & 255;
    const float invN = 1.0f / (float)NN_;
    float m1a = g_sum[c] * invN, m1b = g_sum[c + 1] * invN;
    float v1a = g_sq[c] * invN - m1a * m1a, v1b = g_sq[c + 1] * invN - m1b * m1b;
    float s1a = g1[c] * rsqrtf(v1a + EPS_), s1b = g1[c + 1] * rsqrtf(v1b + EPS_);
    float m2a = g_sum[CC_ + c] * invN, m2b = g_sum[CC_ + c + 1] * invN;
    float v2a = g_sq[CC_ + c] * invN - m2a * m2a, v2b = g_sq[CC_ + c + 1] * invN - m2b * m2b;
    float s2a = g2[c] * rsqrtf(v2a + EPS_), s2b = g2[c + 1] * rsqrtf(v2b + EPS_);
    float2 h1v = upk(*(const uint32_t*)(g_h1_bf + idx));
    float2 h2v = upk(*(const uint32_t*)(g_h2_bf + idx));
    float ya = (h1v.x - m1a) * s1a + b1[c]     + (h2v.x - m2a) * s2a + b2[c];
    float yb = (h1v.y - m1b) * s1b + b1[c + 1] + (h2v.y - m2b) * s2b + b2[c + 1];
    *(uint32_t*)(g_out_bf + idx) = pk(ya, yb);
}

// ---------------- fused pool + head (reads per-graph max/min, no node loop) ----------------
__global__ void pool_head_kernel(const float* __restrict__ g3, const float* __restrict__ b3,
                                 const float* __restrict__ fc_w, const float* __restrict__ fc_b,
                                 float* __restrict__ out) {
    int g = blockIdx.x;
    int c = threadIdx.x;
    __shared__ float pr[CC_];
    __shared__ float lo[NCLS_];
    __shared__ float red[2];
    const float invN = 1.0f / (float)NN_;
    float m3 = g_sum[2 * CC_ + c] * invN;
    float v3 = g_sq[2 * CC_ + c] * invN - m3 * m3;
    float s3 = g3[c] * rsqrtf(v3 + EPS_);
    float sh = b3[c] - m3 * s3;
    float vmax = fdec(g_mx[g * CC_ + c]);
    float vmin = fdec(g_mn[g * CC_ + c]);
    pr[c] = (s3 >= 0.0f) ? fmaf(vmax, s3, sh) : fmaf(vmin, s3, sh);
    __syncthreads();
    if (c < NCLS_) {
        float s = fc_b[c];
        for (int k = 0; k < CC_; k++) s += pr[k] * fc_w[k * NCLS_ + c];
        lo[c] = s;
    }
    __syncthreads();
    if (c == 0) {
        float m = -INFINITY;
        for (int j = 0; j < NCLS_; j++) m = fmaxf(m, lo[j]);
        float se = 0.0f;
        for (int j = 0; j < NCLS_; j++) se += __expf(lo[j] - m);
        red[0] = m;
        red[1] = logf(se);
    }
    __syncthreads();
    if (c < NCLS_) out[g * NCLS_ + c] = lo[c] - red[0] - red[1];
}

// ---------------- launch ----------------
extern "C" void kernel_launch(void* const* d_in, const int* in_sizes, int n_in,
                              void* d_out, int out_size) {
    const float* x          = (const float*)d_in[0];
    const float* W_conv     = (const float*)d_in[1];
    const float* b_conv     = (const float*)d_in[2];
    const float* bn1_g      = (const float*)d_in[3];
    const float* bn1_b      = (const float*)d_in[4];
    const float* in_proj_w  = (const float*)d_in[5];
    const float* in_proj_b  = (const float*)d_in[6];
    const float* out_proj_w = (const float*)d_in[7];
    const float* out_proj_b = (const float*)d_in[8];
    const float* bn2_g      = (const float*)d_in[9];
    const float* bn2_b      = (const float*)d_in[10];
    const float* mlp_w1     = (const float*)d_in[11];
    const float* mlp_b1     = (const float*)d_in[12];
    const float* mlp_w2     = (const float*)d_in[13];
    const float* mlp_b2     = (const float*)d_in[14];
    const float* bn3_g      = (const float*)d_in[15];
    const float* bn3_b      = (const float*)d_in[16];
    const float* fc_w       = (const float*)d_in[17];
    const float* fc_b       = (const float*)d_in[18];
    const int*   edge_index = (const int*)d_in[19];
    float* out = (float*)d_out;

    const int* row = edge_index;
    const int* col = edge_index + EE_;

    cudaFuncSetAttribute(attn_gather, cudaFuncAttributeMaxDynamicSharedMemorySize, AT_SMEM_BYTES);

    float* sum_p;  cudaGetSymbolAddress((void**)&sum_p,  g_sum);
    float* sq_p;   cudaGetSymbolAddress((void**)&sq_p,   g_sq);
    __nv_bfloat16 *hbf_p, *qkvbf_p, *xbf_p, *attnbf_p, *h2bf_p, *outbf_p, *ff1bf_p;
    __nv_bfloat16 *WcT_p, *W1T_p, *W2T_p, *ipw_p, *opw_p;
    cudaGetSymbolAddress((void**)&hbf_p,    g_h_bf);
    cudaGetSymbolAddress((void**)&qkvbf_p,  g_qkv_bf);
    cudaGetSymbolAddress((void**)&xbf_p,    g_x_bf);
    cudaGetSymbolAddress((void**)&attnbf_p, g_attn_bf);
    cudaGetSymbolAddress((void**)&h2bf_p,   g_h2_bf);
    cudaGetSymbolAddress((void**)&outbf_p,  g_out_bf);
    cudaGetSymbolAddress((void**)&ff1bf_p,  g_ff1_bf);
    cudaGetSymbolAddress((void**)&WcT_p,    g_WcT_bf);
    cudaGetSymbolAddress((void**)&W1T_p,    g_W1T_bf);
    cudaGetSymbolAddress((void**)&W2T_p,    g_W2T_bf);
    cudaGetSymbolAddress((void**)&ipw_p,    g_ipw_bf);
    cudaGetSymbolAddress((void**)&opw_p,    g_opw_bf);

    // A: zero, prep
    zero_kernel<<<NN_ / 256, 256>>>();
    prep_kernel<<<4544 + EE_ / 256, 256>>>(W_conv, mlp_w1, mlp_w2, in_proj_w, out_proj_w, x, col);

    // B: fused h|qkv GEMM + scan block
    gemm_mma<4, 0><<<dim3(8, 257), 256, GS3>>>(xbf_p, WcT_p, ipw_p, in_proj_b, nullptr,
                                               nullptr, hbf_p, qkvbf_p, nullptr, nullptr, 0, CC_);
    // C: fill CSR
    fill_kernel<<<EE_ / 256, 256>>>(row, col);

    // D: attention + gather
    attn_gather<<<1024 + NN_ / 8, 256, AT_SMEM_BYTES>>>(qkvbf_p, attnbf_p, x, b_conv);

    // E: out_proj (+stats h2) + stats(h1) blocks
    gemm_mma<5, 2><<<dim3(2, 384), 256, GS3>>>(attnbf_p, opw_p, nullptr, out_proj_b, x,
                                               nullptr, h2bf_p, nullptr, sum_p + CC_, sq_p + CC_, CC_, CC_);
    // F: combine
    combine_kernel<<<NN_ * CC_ / 512, 256>>>(bn1_g, bn1_b, bn2_g, bn2_b);
    // G: ffn1
    gemm_mma<2, 0><<<dim3(4, 256), 256, GS3>>>(outbf_p, W1T_p, nullptr, mlp_b1, nullptr,
                                               nullptr, ff1bf_p, nullptr, nullptr, nullptr, 2 * CC_, CC_);
    // H: ffn2 (bf16 resid, stats + per-graph max/min in epilogue; no out3 store)
    gemm_mma<6, 1><<<dim3(2, 256), 256, GS3>>>(ff1bf_p, W2T_p, nullptr, mlp_b2, nullptr,
                                               nullptr, nullptr, outbf_p, sum_p + 2 * CC_, sq_p + 2 * CC_, CC_, 2 * CC_);
    // I: pool + head (no node loop)
    pool_head_kernel<<<BB_, CC_>>>(bn3_g, bn3_b, fc_w, fc_b, out);
}

// round 16
// speedup vs baseline: 1.0643x; 1.0329x over previous
#include <cuda_runtime.h>
#include <cuda_bf16.h>
#include <math.h>
#include <stdint.h>
#include <stddef.h>

// Problem constants
#define NN_ 32768
#define EE_ 524288
#define CC_ 256
#define HH_ 8
#define BB_ 128
#define NCLS_ 10
#define PER_ 256
#define HD_ 32
#define EPS_ 1e-5f

// ---------------- scratch (static device globals; no allocation) ----------------
__device__ float g_dinv[NN_];
__device__ float g_sum[3 * CC_];
__device__ float g_sq[3 * CC_];
__device__ uint32_t g_mx[BB_ * CC_];
__device__ uint32_t g_mn[BB_ * CC_];
// bf16 operands / intermediates
__device__ __nv_bfloat16 g_h_bf[NN_ * CC_];
__device__ __nv_bfloat16 g_qkv_bf[NN_ * 3 * CC_];
__device__ __nv_bfloat16 g_x_bf[NN_ * CC_];
__device__ __nv_bfloat16 g_attn_bf[NN_ * CC_];
__device__ __nv_bfloat16 g_h1_bf[NN_ * CC_];
__device__ __nv_bfloat16 g_h2_bf[NN_ * CC_];
__device__ __nv_bfloat16 g_out_bf[NN_ * CC_];
__device__ __nv_bfloat16 g_ff1_bf[NN_ * 2 * CC_];
__device__ __nv_bfloat16 g_WcT_bf[CC_ * CC_];
__device__ __nv_bfloat16 g_W1T_bf[2 * CC_ * CC_];
__device__ __nv_bfloat16 g_W2T_bf[CC_ * 2 * CC_];
__device__ __nv_bfloat16 g_ipw_bf[3 * CC_ * CC_];
__device__ __nv_bfloat16 g_opw_bf[CC_ * CC_];
// CSR for gather
__device__ int g_cnt[NN_];
__device__ int g_off[NN_ + 1];
__device__ int g_cur[NN_];
__device__ int g_src[EE_];

// ---------------- helpers ----------------
__device__ __forceinline__ uint32_t smem_u32(const void* p) {
    uint32_t a;
    asm("{ .reg .u64 t; cvta.to.shared.u64 t, %1; cvt.u32.u64 %0, t; }" : "=r"(a) : "l"(p));
    return a;
}
#define CP_COMMIT() asm volatile("cp.async.commit_group;" ::: "memory")
#define CP_WAIT1() asm volatile("cp.async.wait_group 1;" ::: "memory")
#define CP_WAIT0() asm volatile("cp.async.wait_group 0;" ::: "memory")

__device__ __forceinline__ uint32_t pk(float lo, float hi) {
    uint32_t r;
    asm("cvt.rn.bf16x2.f32 %0, %1, %2;" : "=r"(r) : "f"(hi), "f"(lo));
    return r;
}
__device__ __forceinline__ float2 upk(uint32_t w) {
    __nv_bfloat162 t = *(__nv_bfloat162*)&w;
    return __bfloat1622float2(t);
}
// monotone float<->uint encoding for atomicMax/Min
__device__ __forceinline__ uint32_t fenc(float f) {
    uint32_t u = __float_as_uint(f);
    return (u & 0x80000000u) ? ~u : (u | 0x80000000u);
}
__device__ __forceinline__ float fdec(uint32_t e) {
    uint32_t u = (e & 0x80000000u) ? (e & 0x7FFFFFFFu) : ~e;
    return __uint_as_float(u);
}
__device__ __forceinline__ void mma16(float* c, const uint32_t* a, const uint32_t* b) {
    asm volatile("mma.sync.aligned.m16n8k16.row.col.f32.bf16.bf16.f32 "
        "{%0,%1,%2,%3}, {%4,%5,%6,%7}, {%8,%9}, {%0,%1,%2,%3};"
        : "+f"(c[0]), "+f"(c[1]), "+f"(c[2]), "+f"(c[3])
        : "r"(a[0]), "r"(a[1]), "r"(a[2]), "r"(a[3]), "r"(b[0]), "r"(b[1]));
}
__device__ __forceinline__ void ldsm4(uint32_t* r, uint32_t addr) {
    asm volatile("ldmatrix.sync.aligned.m8n8.x4.shared.b16 {%0,%1,%2,%3}, [%4];"
        : "=r"(r[0]), "=r"(r[1]), "=r"(r[2]), "=r"(r[3]) : "r"(addr));
}
__device__ __forceinline__ float fast_exp2(float z) {
    float fz = z + 12582912.0f;
    int n = __float_as_int(fz) - 0x4B400000;
    float f = z - (fz - 12582912.0f);
    float p = 0.0013333558f;
    p = fmaf(p, f, 0.0096181291f);
    p = fmaf(p, f, 0.0555041087f);
    p = fmaf(p, f, 0.2402265070f);
    p = fmaf(p, f, 0.6931471806f);
    p = fmaf(p, f, 1.0f);
    return p * __int_as_float((n + 127) << 23);
}
#define ATT_C (1.4426950408889634f * 0.17677669529663687f)
__device__ __forceinline__ float fast_exp_s(float s) { return fast_exp2(s * ATT_C); }

// ---------------- zero ----------------
__global__ void zero_kernel() {
    int i = blockIdx.x * blockDim.x + threadIdx.x;
    if (i < NN_) {
        g_cnt[i] = 0;
        g_mx[i] = 0u;
        g_mn[i] = 0xFFFFFFFFu;
    }
    if (i < 3 * CC_) { g_sum[i] = 0.0f; g_sq[i] = 0.0f; }
}

// ---------------- prep ----------------
__device__ __forceinline__ void transpose_tile_bf(const float* __restrict__ in, __nv_bfloat16* __restrict__ out,
                                                  int R, int Cc, int bx, int by) {
    __shared__ float t[32][33];
    int tx = threadIdx.x & 31, ty = threadIdx.x >> 5;
    int x = bx * 32 + tx;
    #pragma unroll
    for (int i = 0; i < 32; i += 8) t[ty + i][tx] = in[(size_t)(by * 32 + ty + i) * Cc + x];
    __syncthreads();
    int xo = by * 32 + tx;
    #pragma unroll
    for (int i = 0; i < 32; i += 8)
        out[(size_t)(bx * 32 + ty + i) * R + xo] = __float2bfloat16(t[tx][ty + i]);
}

__device__ __forceinline__ void conv_range(const float* __restrict__ in, __nv_bfloat16* __restrict__ out,
                                           int blk, int tid) {
    int base = blk * 2048 + tid * 8;
    float4 v0 = *(const float4*)(in + base);
    float4 v1 = *(const float4*)(in + base + 4);
    uint32_t* o = (uint32_t*)(out + base);
    o[0] = pk(v0.x, v0.y); o[1] = pk(v0.z, v0.w);
    o[2] = pk(v1.x, v1.y); o[3] = pk(v1.z, v1.w);
}

__global__ void __launch_bounds__(256) prep_kernel(const float* __restrict__ W_conv,
                                                   const float* __restrict__ mlp_w1,
                                                   const float* __restrict__ mlp_w2,
                                                   const float* __restrict__ in_proj_w,
                                                   const float* __restrict__ out_proj_w,
                                                   const float* __restrict__ x,
                                                   const int* __restrict__ col) {
    int b = blockIdx.x;
    int tid = threadIdx.x;
    if (b < 64) {
        transpose_tile_bf(W_conv, g_WcT_bf, CC_, CC_, b & 7, b >> 3);
    } else if (b < 192) {
        int bb = b - 64;
        transpose_tile_bf(mlp_w1, g_W1T_bf, CC_, 2 * CC_, bb & 15, bb >> 4);
    } else if (b < 320) {
        int bb = b - 192;
        transpose_tile_bf(mlp_w2, g_W2T_bf, 2 * CC_, CC_, bb & 7, bb >> 3);
    } else if (b < 416) {
        conv_range(in_proj_w, g_ipw_bf, b - 320, tid);
    } else if (b < 448) {
        conv_range(out_proj_w, g_opw_bf, b - 416, tid);
    } else if (b < 4544) {
        conv_range(x, g_x_bf, b - 448, tid);
    } else {
        int e = (b - 4544) * 256 + tid;
        if (e < EE_) atomicAdd(&g_cnt[col[e]], 1);
    }
}

// ---------------- scan body (256 threads; scheduled FIRST inside EPI4 launch) ----------------
__device__ void scan_body() {
    __shared__ int sp[256];
    int t = threadIdx.x;
    int base = t * 128;
    int run = 0;
    for (int i = 0; i < 128; i++) run += g_cnt[base + i];
    sp[t] = run;
    __syncthreads();
    for (int d = 1; d < 256; d <<= 1) {
        int v = sp[t];
        int u = (t >= d) ? sp[t - d] : 0;
        __syncthreads();
        sp[t] = v + u;
        __syncthreads();
    }
    int o = (t > 0) ? sp[t - 1] : 0;
    for (int i = 0; i < 128; i++) {
        int cnt = g_cnt[base + i];
        g_off[base + i] = o;
        g_cur[base + i] = o;
        g_dinv[base + i] = rsqrtf((float)(cnt + 1));
        o += cnt;
    }
    if (t == 255) g_off[NN_] = EE_;
}

// ---------------- fill CSR (2 edges/thread) ----------------
__global__ void fill_kernel(const int* __restrict__ row, const int* __restrict__ col) {
    int e0 = (blockIdx.x * blockDim.x + threadIdx.x) * 2;
    #pragma unroll
    for (int k = 0; k < 2; k++) {
        int e = e0 + k;
        if (e < EE_) {
            int c = col[e];
            int p = atomicAdd(&g_cur[c], 1);
            g_src[p] = row[e];
        }
    }
}

// ---------------- gather body ----------------
__device__ __forceinline__ void acc8(float* acc, float w, uint4 u) {
    float2 f0 = upk(u.x), f1 = upk(u.y), f2 = upk(u.z), f3 = upk(u.w);
    acc[0] = fmaf(w, f0.x, acc[0]); acc[1] = fmaf(w, f0.y, acc[1]);
    acc[2] = fmaf(w, f1.x, acc[2]); acc[3] = fmaf(w, f1.y, acc[3]);
    acc[4] = fmaf(w, f2.x, acc[4]); acc[5] = fmaf(w, f2.y, acc[5]);
    acc[6] = fmaf(w, f3.x, acc[6]); acc[7] = fmaf(w, f3.y, acc[7]);
}

__device__ void gather_node(int gw, int lane, const float* __restrict__ x,
                            const float* __restrict__ b_conv) {
    int beg = g_off[gw], end = g_off[gw + 1];
    float acc[8] = {0, 0, 0, 0, 0, 0, 0, 0};
    for (int e0 = beg; e0 < end; e0 += 32) {
        int nb = min(32, end - e0);
        int src = (e0 + lane < end) ? g_src[e0 + lane] : 0;
        int j = 0;
        for (; j + 4 <= nb; j += 4) {
            int r0 = __shfl_sync(0xFFFFFFFF, src, j);
            int r1 = __shfl_sync(0xFFFFFFFF, src, j + 1);
            int r2 = __shfl_sync(0xFFFFFFFF, src, j + 2);
            int r3 = __shfl_sync(0xFFFFFFFF, src, j + 3);
            float w0 = g_dinv[r0], w1 = g_dinv[r1], w2 = g_dinv[r2], w3 = g_dinv[r3];
            uint4 u0 = *((const uint4*)(g_h_bf + (size_t)r0 * CC_) + lane);
            uint4 u1 = *((const uint4*)(g_h_bf + (size_t)r1 * CC_) + lane);
            uint4 u2 = *((const uint4*)(g_h_bf + (size_t)r2 * CC_) + lane);
            uint4 u3 = *((const uint4*)(g_h_bf + (size_t)r3 * CC_) + lane);
            acc8(acc, w0, u0); acc8(acc, w1, u1); acc8(acc, w2, u2); acc8(acc, w3, u3);
        }
        for (; j < nb; j++) {
            int r = __shfl_sync(0xFFFFFFFF, src, j);
            float w = g_dinv[r];
            uint4 u = *((const uint4*)(g_h_bf + (size_t)r * CC_) + lane);
            acc8(acc, w, u);
        }
    }
    float dn = g_dinv[gw];
    float dn2 = dn * dn;
    float self[8] = {0, 0, 0, 0, 0, 0, 0, 0};
    uint4 us = *((const uint4*)(g_h_bf + (size_t)gw * CC_) + lane);
    acc8(self, 1.0f, us);
    const float4* xn = (const float4*)(x + (size_t)gw * CC_) + lane * 2;
    const float4* bc = (const float4*)b_conv + lane * 2;
    float4 x0 = xn[0], x1 = xn[1];
    float4 b0 = bc[0], b1 = bc[1];
    float4 o0, o1;
    o0.x = fmaf(dn, acc[0], fmaf(dn2, self[0], b0.x + x0.x));
    o0.y = fmaf(dn, acc[1], fmaf(dn2, self[1], b0.y + x0.y));
    o0.z = fmaf(dn, acc[2], fmaf(dn2, self[2], b0.z + x0.z));
    o0.w = fmaf(dn, acc[3], fmaf(dn2, self[3], b0.w + x0.w));
    o1.x = fmaf(dn, acc[4], fmaf(dn2, self[4], b1.x + x1.x));
    o1.y = fmaf(dn, acc[5], fmaf(dn2, self[5], b1.y + x1.y));
    o1.z = fmaf(dn, acc[6], fmaf(dn2, self[6], b1.z + x1.z));
    o1.w = fmaf(dn, acc[7], fmaf(dn2, self[7], b1.w + x1.w));
    uint4 ov;
    ov.x = pk(o0.x, o0.y); ov.y = pk(o0.z, o0.w);
    ov.z = pk(o1.x, o1.y); ov.w = pk(o1.z, o1.w);
    *((uint4*)(g_h1_bf + (size_t)gw * CC_) + lane) = ov;
}

// ---------------- bf16 GEMM: 128x128 tile, K-chunk 32, 2-stage, ldmatrix ----
// EPI: 2 bias+relu->bf16 | 4 split h|qkv ->bf16 (+scan at block (0,0)) |
//      5 bias+fp32resid->bf16 | 6 bias+bf16resid-> per-graph max/min only
// STATS: 0 none | 1 epilogue col-stats | 2 epilogue col-stats + h1-stats blocks (FIRST)
#define CHUNK_B 10240
#define BUF_B (2 * CHUNK_B)
#define GS3 (2 * BUF_B + 2048)

__device__ __forceinline__ void ld_chunk_bf(uint32_t dst, const __nv_bfloat16* __restrict__ g,
                                            int ld, int row0, int k0, int tid) {
    #pragma unroll
    for (int i = 0; i < 2; i++) {
        int seg = i * 256 + tid;
        int r = seg >> 2, s = seg & 3;
        uint32_t d = dst + (uint32_t)(r * 80 + s * 16);
        const __nv_bfloat16* src = g + (size_t)(row0 + r) * ld + k0 + s * 8;
        asm volatile("cp.async.cg.shared.global [%0], [%1], 16;" :: "r"(d), "l"(src));
    }
}

template<int EPI, int STATS>
__global__ void __launch_bounds__(256, 2) gemm_mma(
    const __nv_bfloat16* __restrict__ A, const __nv_bfloat16* __restrict__ Bt,
    const __nv_bfloat16* __restrict__ Bt2,
    const float* __restrict__ bias, const float* __restrict__ resid,
    float* __restrict__ C, __nv_bfloat16* __restrict__ Cbf, __nv_bfloat16* __restrict__ C2bf,
    float* __restrict__ gsum, float* __restrict__ gsq, int Nn, int K)
{
    int ybase = 0;
    if (EPI == 4) {
        // scan rides at y==0 so it runs in the first wave
        if (blockIdx.y == 0) {
            if (blockIdx.x == 0) scan_body();
            return;
        }
        ybase = 1;
    }
    if (STATS == 2) {
        // h1-stats blocks ride at y<128 so they run in the first waves
        if (blockIdx.y < 128) {
            int idxb = blockIdx.y * gridDim.x + blockIdx.x;
            int r0 = idxb * 128;
            int cch = threadIdx.x;
            float s = 0.0f, q = 0.0f;
            #pragma unroll 4
            for (int r = 0; r < 128; r++) {
                float v = __bfloat162float(g_h1_bf[(size_t)(r0 + r) * CC_ + cch]);
                s += v; q += v * v;
            }
            atomicAdd(&g_sum[cch], s);
            atomicAdd(&g_sq[cch], q);
            return;
        }
        ybase = 128;
    }

    extern __shared__ char smc[];
    uint32_t sb = smem_u32(smc);
    float* ssum = (float*)(smc + 2 * BUF_B);
    float* ssq  = ssum + 128;
    uint32_t* smx = (uint32_t*)(ssq + 128);
    uint32_t* smn = smx + 128;
    int tid = threadIdx.x;
    int wid = tid >> 5, lane = tid & 31;
    int grp = lane >> 2, qd = lane & 3;
    int wm = wid >> 1, wn = wid & 1;
    int row0 = (blockIdx.y - ybase) * 128, col0 = blockIdx.x * 128;

    if (STATS && tid < 256) ((float*)(smc + 2 * BUF_B))[tid] = 0.0f;
    if (EPI == 6 && tid < 128) { smx[tid] = 0u; smn[tid] = 0xFFFFFFFFu; }

    const __nv_bfloat16* Bsrc = Bt;
    int bro = col0;
    if (EPI == 4 && col0 >= 256) { Bsrc = Bt2; bro = col0 - 256; }

    int lrow = lane & 15, lhalf = lane >> 4;
    uint32_t aaddr[2];
    #pragma unroll
    for (int mf = 0; mf < 2; mf++)
        aaddr[mf] = sb + (uint32_t)((wm * 32 + mf * 16 + lrow) * 80 + lhalf * 16);
    int brow = (lane & 7) + ((lane >> 4) << 3);
    int bhalf = (lane >> 3) & 1;
    uint32_t baddr[4];
    #pragma unroll
    for (int p = 0; p < 4; p++)
        baddr[p] = sb + CHUNK_B + (uint32_t)((wn * 64 + 16 * p + brow) * 80 + bhalf * 16);

    float acc[2][8][4];
    #pragma unroll
    for (int mf = 0; mf < 2; mf++)
        #pragma unroll
        for (int nf = 0; nf < 8; nf++)
            #pragma unroll
            for (int j = 0; j < 4; j++) acc[mf][nf][j] = 0.0f;

    int nch = K >> 5;
    ld_chunk_bf(sb, A, K, row0, 0, tid);
    ld_chunk_bf(sb + CHUNK_B, Bsrc, K, bro, 0, tid);
    CP_COMMIT();

    for (int c = 0; c < nch; c++) {
        int s = c & 1;
        if (c + 1 < nch) {
            int s2 = s ^ 1;
            ld_chunk_bf(sb + (uint32_t)(s2 * BUF_B), A, K, row0, (c + 1) << 5, tid);
            ld_chunk_bf(sb + (uint32_t)(s2 * BUF_B) + CHUNK_B, Bsrc, K, bro, (c + 1) << 5, tid);
            CP_COMMIT();
            CP_WAIT1();
        } else {
            CP_WAIT0();
        }
        __syncthreads();
        uint32_t stoff = (uint32_t)(s * BUF_B);
        #pragma unroll
        for (int kk = 0; kk < 2; kk++) {
            uint32_t ko = stoff + kk * 32;
            uint32_t a[2][4], b[8][2];
            ldsm4(a[0], aaddr[0] + ko);
            ldsm4(a[1], aaddr[1] + ko);
            #pragma unroll
            for (int p = 0; p < 4; p++) {
                uint32_t t4[4];
                ldsm4(t4, baddr[p] + ko);
                b[2 * p][0] = t4[0]; b[2 * p][1] = t4[1];
                b[2 * p + 1][0] = t4[2]; b[2 * p + 1][1] = t4[3];
            }
            #pragma unroll
            for (int mf = 0; mf < 2; mf++)
                #pragma unroll
                for (int nf = 0; nf < 8; nf++)
                    mma16(acc[mf][nf], a[mf], b[nf]);
        }
        __syncthreads();
    }

    #pragma unroll
    for (int nf = 0; nf < 8; nf++) {
        float sc0 = 0, sc1 = 0, qc0 = 0, qc1 = 0;
        float mx0 = -INFINITY, mx1 = -INFINITY, mn0 = INFINITY, mn1 = INFINITY;
        #pragma unroll
        for (int mf = 0; mf < 2; mf++) {
            int r1 = row0 + wm * 32 + mf * 16 + grp;
            int cc = col0 + wn * 64 + nf * 8 + qd * 2;
            float2 v0 = make_float2(acc[mf][nf][0], acc[mf][nf][1]);
            float2 v1 = make_float2(acc[mf][nf][2], acc[mf][nf][3]);
            if (EPI == 2 || EPI == 5 || EPI == 6) {
                float b0 = bias[cc], b1 = bias[cc + 1];
                v0.x += b0; v0.y += b1; v1.x += b0; v1.y += b1;
            }
            if (EPI == 2) {
                v0.x = fmaxf(v0.x, 0.0f); v0.y = fmaxf(v0.y, 0.0f);
                v1.x = fmaxf(v1.x, 0.0f); v1.y = fmaxf(v1.y, 0.0f);
                *(uint32_t*)(Cbf + (size_t)r1 * Nn + cc) = pk(v0.x, v0.y);
                *(uint32_t*)(Cbf + (size_t)(r1 + 8) * Nn + cc) = pk(v1.x, v1.y);
            }
            if (EPI == 5) {
                float2 ra = *(const float2*)(resid + (size_t)r1 * Nn + cc);
                float2 rb = *(const float2*)(resid + (size_t)(r1 + 8) * Nn + cc);
                v0.x += ra.x; v0.y += ra.y; v1.x += rb.x; v1.y += rb.y;
                *(uint32_t*)(Cbf + (size_t)r1 * Nn + cc) = pk(v0.x, v0.y);
                *(uint32_t*)(Cbf + (size_t)(r1 + 8) * Nn + cc) = pk(v1.x, v1.y);
            }
            if (EPI == 6) {
                uint32_t ra = *(const uint32_t*)(C2bf + (size_t)r1 * Nn + cc);
                uint32_t rb = *(const uint32_t*)(C2bf + (size_t)(r1 + 8) * Nn + cc);
                float2 fa = upk(ra), fb = upk(rb);
                v0.x += fa.x; v0.y += fa.y; v1.x += fb.x; v1.y += fb.y;
                mx0 = fmaxf(mx0, fmaxf(v0.x, v1.x));
                mx1 = fmaxf(mx1, fmaxf(v0.y, v1.y));
                mn0 = fminf(mn0, fminf(v0.x, v1.x));
                mn1 = fminf(mn1, fminf(v0.y, v1.y));
            }
            if (EPI == 4) {
                if (col0 < 256) {
                    *(uint32_t*)(Cbf + (size_t)r1 * CC_ + cc) = pk(v0.x, v0.y);
                    *(uint32_t*)(Cbf + (size_t)(r1 + 8) * CC_ + cc) = pk(v1.x, v1.y);
                } else {
                    int cq = cc - 256;
                    float b0 = bias[cq], b1 = bias[cq + 1];
                    v0.x += b0; v0.y += b1; v1.x += b0; v1.y += b1;
                    *(uint32_t*)(C2bf + (size_t)r1 * (3 * CC_) + cq) = pk(v0.x, v0.y);
                    *(uint32_t*)(C2bf + (size_t)(r1 + 8) * (3 * CC_) + cq) = pk(v1.x, v1.y);
                }
            }
            if (STATS) {
                sc0 += v0.x + v1.x; sc1 += v0.y + v1.y;
                qc0 += v0.x * v0.x + v1.x * v1.x;
                qc1 += v0.y * v0.y + v1.y * v1.y;
            }
        }
        if (STATS) {
            #pragma unroll
            for (int m = 4; m <= 16; m <<= 1) {
                sc0 += __shfl_xor_sync(0xFFFFFFFF, sc0, m);
                sc1 += __shfl_xor_sync(0xFFFFFFFF, sc1, m);
                qc0 += __shfl_xor_sync(0xFFFFFFFF, qc0, m);
                qc1 += __shfl_xor_sync(0xFFFFFFFF, qc1, m);
            }
            if (lane < 4) {
                int ci = wn * 64 + nf * 8 + qd * 2;
                atomicAdd(&ssum[ci], sc0); atomicAdd(&ssum[ci + 1], sc1);
                atomicAdd(&ssq[ci], qc0);  atomicAdd(&ssq[ci + 1], qc1);
            }
        }
        if (EPI == 6) {
            #pragma unroll
            for (int m = 4; m <= 16; m <<= 1) {
                mx0 = fmaxf(mx0, __shfl_xor_sync(0xFFFFFFFF, mx0, m));
                mx1 = fmaxf(mx1, __shfl_xor_sync(0xFFFFFFFF, mx1, m));
                mn0 = fminf(mn0, __shfl_xor_sync(0xFFFFFFFF, mn0, m));
                mn1 = fminf(mn1, __shfl_xor_sync(0xFFFFFFFF, mn1, m));
            }
            if (lane < 4) {
                int ci = wn * 64 + nf * 8 + qd * 2;
                atomicMax(&smx[ci], fenc(mx0)); atomicMax(&smx[ci + 1], fenc(mx1));
                atomicMin(&smn[ci], fenc(mn0)); atomicMin(&smn[ci + 1], fenc(mn1));
            }
        }
    }
    if (STATS || EPI == 6) {
        __syncthreads();
        if (tid < 128) {
            if (STATS) {
                atomicAdd(&gsum[col0 + tid], ssum[tid]);
                atomicAdd(&gsq[col0 + tid], ssq[tid]);
            }
            if (EPI == 6) {
                int graph = row0 >> 8;
                atomicMax(&g_mx[graph * CC_ + col0 + tid], smx[tid]);
                atomicMin(&g_mn[graph * CC_ + col0 + tid], smn[tid]);
            }
        }
    }
}

// ---------------- fused attention (blocks <1024) + gather (blocks >=1024) ----------------
#define AT_VT_OFF 5120
#define AT_SMEM_BYTES ((5120 + 32 * 132) * 4)

__global__ void __launch_bounds__(256) attn_gather(const __nv_bfloat16* __restrict__ qkv,
                                                   __nv_bfloat16* __restrict__ outbf,
                                                   const float* __restrict__ x,
                                                   const float* __restrict__ b_conv) {
    int tid = threadIdx.x;
    if (blockIdx.x >= 1024) {
        int gw = (blockIdx.x - 1024) * 8 + (tid >> 5);
        gather_node(gw, tid & 31, x, b_conv);
        return;
    }
    extern __shared__ uint32_t smw[];
    uint32_t* Ks = smw;
    uint32_t* Vt = smw + AT_VT_OFF;
    const uint32_t* qw = (const uint32_t*)qkv;
    int wid = tid >> 5, lane = tid & 31;
    int grp = lane >> 2, qd = lane & 3;
    int bx = blockIdx.x;
    int b = bx >> 3, h = bx & 7;
    int base = b * PER_;
    int m0 = wid * 32;

    for (int i = tid; i < 4096; i += 256) {
        int key = i >> 4, w = i & 15;
        Ks[key * 20 + w] = qw[(size_t)(base + key) * 384 + 128 + h * 16 + w];
    }
    {
        __nv_bfloat16* VtB = (__nv_bfloat16*)Vt;
        for (int i = tid; i < 4096; i += 256) {
            int key = i >> 4, w = i & 15;
            uint32_t u = qw[(size_t)(base + key) * 384 + 256 + h * 16 + w];
            __nv_bfloat162 t = *(__nv_bfloat162*)&u;
            VtB[(2 * w) * 264 + key] = t.x;
            VtB[(2 * w + 1) * 264 + key] = t.y;
        }
    }
    uint32_t qf[2][2][4];
    #pragma unroll
    for (int mf = 0; mf < 2; mf++) {
        size_t r0 = (size_t)(base + m0 + mf * 16 + grp) * 384 + h * 16;
        size_t r1 = r0 + 8 * 384;
        #pragma unroll
        for (int kt = 0; kt < 2; kt++) {
            qf[mf][kt][0] = qw[r0 + kt * 8 + qd];
            qf[mf][kt][1] = qw[r1 + kt * 8 + qd];
            qf[mf][kt][2] = qw[r0 + kt * 8 + qd + 4];
            qf[mf][kt][3] = qw[r1 + kt * 8 + qd + 4];
        }
    }
    __syncthreads();

    float oacc[2][4][4];
    #pragma unroll
    for (int mf = 0; mf < 2; mf++)
        #pragma unroll
        for (int nf = 0; nf < 4; nf++)
            #pragma unroll
            for (int j = 0; j < 4; j++) oacc[mf][nf][j] = 0.0f;
    float den[2][2] = {{0.0f, 0.0f}, {0.0f, 0.0f}};

    for (int ct = 0; ct < 8; ct++) {
        float sx[2][4][4];
        #pragma unroll
        for (int mf = 0; mf < 2; mf++)
            #pragma unroll
            for (int nf = 0; nf < 4; nf++)
                #pragma unroll
                for (int j = 0; j < 4; j++) sx[mf][nf][j] = 0.0f;
        #pragma unroll
        for (int nf = 0; nf < 4; nf++) {
            const uint32_t* kr = Ks + (ct * 32 + nf * 8 + grp) * 20;
            #pragma unroll
            for (int kt = 0; kt < 2; kt++) {
                uint32_t bb[2];
                bb[0] = kr[kt * 8 + qd];
                bb[1] = kr[kt * 8 + qd + 4];
                mma16(sx[0][nf], qf[0][kt], bb);
                mma16(sx[1][nf], qf[1][kt], bb);
            }
        }
        #pragma unroll
        for (int mf = 0; mf < 2; mf++)
            #pragma unroll
            for (int nf = 0; nf < 4; nf++) {
                float w0 = fast_exp_s(sx[mf][nf][0]);
                float w1 = fast_exp_s(sx[mf][nf][1]);
                float w2 = fast_exp_s(sx[mf][nf][2]);
                float w3 = fast_exp_s(sx[mf][nf][3]);
                den[mf][0] += w0 + w1;
                den[mf][1] += w2 + w3;
                sx[mf][nf][0] = w0; sx[mf][nf][1] = w1;
                sx[mf][nf][2] = w2; sx[mf][nf][3] = w3;
            }
        #pragma unroll
        for (int kt = 0; kt < 2; kt++) {
            uint32_t pa[2][4];
            #pragma unroll
            for (int mf = 0; mf < 2; mf++) {
                pa[mf][0] = pk(sx[mf][2 * kt][0],     sx[mf][2 * kt][1]);
                pa[mf][1] = pk(sx[mf][2 * kt][2],     sx[mf][2 * kt][3]);
                pa[mf][2] = pk(sx[mf][2 * kt + 1][0], sx[mf][2 * kt + 1][1]);
                pa[mf][3] = pk(sx[mf][2 * kt + 1][2], sx[mf][2 * kt + 1][3]);
            }
            #pragma unroll
            for (int nf = 0; nf < 4; nf++) {
                const uint32_t* vr = Vt + (nf * 8 + grp) * 132 + ct * 16 + kt * 8;
                uint32_t bb[2];
                bb[0] = vr[qd];
                bb[1] = vr[qd + 4];
                mma16(oacc[0][nf], pa[0], bb);
                mma16(oacc[1][nf], pa[1], bb);
            }
        }
    }

    #pragma unroll
    for (int mf = 0; mf < 2; mf++)
        #pragma unroll
        for (int r = 0; r < 2; r++) {
            float d = den[mf][r];
            d += __shfl_xor_sync(0xFFFFFFFF, d, 1);
            d += __shfl_xor_sync(0xFFFFFFFF, d, 2);
            den[mf][r] = 1.0f / d;
        }
    #pragma unroll
    for (int mf = 0; mf < 2; mf++) {
        int r0 = base + m0 + mf * 16 + grp;
        #pragma unroll
        for (int nf = 0; nf < 4; nf++) {
            int colx = h * HD_ + nf * 8 + 2 * qd;
            *(uint32_t*)(outbf + (size_t)r0 * CC_ + colx) =
                pk(oacc[mf][nf][0] * den[mf][0], oacc[mf][nf][1] * den[mf][0]);
            *(uint32_t*)(outbf + (size_t)(r0 + 8) * CC_ + colx) =
                pk(oacc[mf][nf][2] * den[mf][1], oacc[mf][nf][3] * den[mf][1]);
        }
    }
}

// ---------------- combine: out = BN1(h1) + BN2(h2), bf16 in/out, 8 elems/thread ----------------
__global__ void combine_kernel(const float* __restrict__ g1, const float* __restrict__ b1,
                               const float* __restrict__ g2, const float* __restrict__ b2) {
    int gid = blockIdx.x * blockDim.x + threadIdx.x;
    int idx = gid * 8;
    if (idx >= NN_ * CC_) return;
    int c = idx & 255;
    const float invN = 1.0f / (float)NN_;
    uint4 u1 = *(const uint4*)(g_h1_bf + idx);
    uint4 u2 = *(const uint4*)(g_h2_bf + idx);
    const uint32_t w1[4] = {u1.x, u1.y, u1.z, u1.w};
    const uint32_t w2[4] = {u2.x, u2.y, u2.z, u2.w};
    uint4 ov;
    uint32_t* op = (uint32_t*)&ov;
    #pragma unroll
    for (int p = 0; p < 4; p++) {
        int ca = c + 2 * p, cb = ca + 1;
        float m1a = g_sum[ca] * invN, m1b = g_sum[cb] * invN;
        float v1a = g_sq[ca] * invN - m1a * m1a, v1b = g_sq[cb] * invN - m1b * m1b;
        float s1a = g1[ca] * rsqrtf(v1a + EPS_), s1b = g1[cb] * rsqrtf(v1b + EPS_);
        float m2a = g_sum[CC_ + ca] * invN, m2b = g_sum[CC_ + cb] * invN;
        float v2a = g_sq[CC_ + ca] * invN - m2a * m2a, v2b = g_sq[CC_ + cb] * invN - m2b * m2b;
        float s2a = g2[ca] * rsqrtf(v2a + EPS_), s2b = g2[cb] * rsqrtf(v2b + EPS_);
        float2 h1v = upk(w1[p]);
        float2 h2v = upk(w2[p]);
        float ya = (h1v.x - m1a) * s1a + b1[ca] + (h2v.x - m2a) * s2a + b2[ca];
        float yb = (h1v.y - m1b) * s1b + b1[cb] + (h2v.y - m2b) * s2b + b2[cb];
        op[p] = pk(ya, yb);
    }
    *(uint4*)(g_out_bf + idx) = ov;
}

// ---------------- fused pool + head ----------------
__global__ void pool_head_kernel(const float* __restrict__ g3, const float* __restrict__ b3,
                                 const float* __restrict__ fc_w, const float* __restrict__ fc_b,
                                 float* __restrict__ out) {
    int g = blockIdx.x;
    int c = threadIdx.x;
    __shared__ float pr[CC_];
    __shared__ float lo[NCLS_];
    __shared__ float red[2];
    const float invN = 1.0f / (float)NN_;
    float m3 = g_sum[2 * CC_ + c] * invN;
    float v3 = g_sq[2 * CC_ + c] * invN - m3 * m3;
    float s3 = g3[c] * rsqrtf(v3 + EPS_);
    float sh = b3[c] - m3 * s3;
    float vmax = fdec(g_mx[g * CC_ + c]);
    float vmin = fdec(g_mn[g * CC_ + c]);
    pr[c] = (s3 >= 0.0f) ? fmaf(vmax, s3, sh) : fmaf(vmin, s3, sh);
    __syncthreads();
    if (c < NCLS_) {
        float s = fc_b[c];
        for (int k = 0; k < CC_; k++) s += pr[k] * fc_w[k * NCLS_ + c];
        lo[c] = s;
    }
    __syncthreads();
    if (c == 0) {
        float m = -INFINITY;
        for (int j = 0; j < NCLS_; j++) m = fmaxf(m, lo[j]);
        float se = 0.0f;
        for (int j = 0; j < NCLS_; j++) se += __expf(lo[j] - m);
        red[0] = m;
        red[1] = logf(se);
    }
    __syncthreads();
    if (c < NCLS_) out[g * NCLS_ + c] = lo[c] - red[0] - red[1];
}

// ---------------- launch ----------------
extern "C" void kernel_launch(void* const* d_in, const int* in_sizes, int n_in,
                              void* d_out, int out_size) {
    const float* x          = (const float*)d_in[0];
    const float* W_conv     = (const float*)d_in[1];
    const float* b_conv     = (const float*)d_in[2];
    const float* bn1_g      = (const float*)d_in[3];
    const float* bn1_b      = (const float*)d_in[4];
    const float* in_proj_w  = (const float*)d_in[5];
    const float* in_proj_b  = (const float*)d_in[6];
    const float* out_proj_w = (const float*)d_in[7];
    const float* out_proj_b = (const float*)d_in[8];
    const float* bn2_g      = (const float*)d_in[9];
    const float* bn2_b      = (const float*)d_in[10];
    const float* mlp_w1     = (const float*)d_in[11];
    const float* mlp_b1     = (const float*)d_in[12];
    const float* mlp_w2     = (const float*)d_in[13];
    const float* mlp_b2     = (const float*)d_in[14];
    const float* bn3_g      = (const float*)d_in[15];
    const float* bn3_b      = (const float*)d_in[16];
    const float* fc_w       = (const float*)d_in[17];
    const float* fc_b       = (const float*)d_in[18];
    const int*   edge_index = (const int*)d_in[19];
    float* out = (float*)d_out;

    const int* row = edge_index;
    const int* col = edge_index + EE_;

    cudaFuncSetAttribute(attn_gather, cudaFuncAttributeMaxDynamicSharedMemorySize, AT_SMEM_BYTES);

    float* sum_p;  cudaGetSymbolAddress((void**)&sum_p,  g_sum);
    float* sq_p;   cudaGetSymbolAddress((void**)&sq_p,   g_sq);
    __nv_bfloat16 *hbf_p, *qkvbf_p, *xbf_p, *attnbf_p, *h2bf_p, *outbf_p, *ff1bf_p;
    __nv_bfloat16 *WcT_p, *W1T_p, *W2T_p, *ipw_p, *opw_p;
    cudaGetSymbolAddress((void**)&hbf_p,    g_h_bf);
    cudaGetSymbolAddress((void**)&qkvbf_p,  g_qkv_bf);
    cudaGetSymbolAddress((void**)&xbf_p,    g_x_bf);
    cudaGetSymbolAddress((void**)&attnbf_p, g_attn_bf);
    cudaGetSymbolAddress((void**)&h2bf_p,   g_h2_bf);
    cudaGetSymbolAddress((void**)&outbf_p,  g_out_bf);
    cudaGetSymbolAddress((void**)&ff1bf_p,  g_ff1_bf);
    cudaGetSymbolAddress((void**)&WcT_p,    g_WcT_bf);
    cudaGetSymbolAddress((void**)&W1T_p,    g_W1T_bf);
    cudaGetSymbolAddress((void**)&W2T_p,    g_W2T_bf);
    cudaGetSymbolAddress((void**)&ipw_p,    g_ipw_bf);
    cudaGetSymbolAddress((void**)&opw_p,    g_opw_bf);

    // A: zero, prep
    zero_kernel<<<NN_ / 256, 256>>>();
    prep_kernel<<<4544 + EE_ / 256, 256>>>(W_conv, mlp_w1, mlp_w2, in_proj_w, out_proj_w, x, col);

    // B: fused h|qkv GEMM + scan block (scan at y=0, runs first)
    gemm_mma<4, 0><<<dim3(8, 257), 256, GS3>>>(xbf_p, WcT_p, ipw_p, in_proj_b, nullptr,
                                               nullptr, hbf_p, qkvbf_p, nullptr, nullptr, 0, CC_);
    // C: fill CSR
    fill_kernel<<<EE_ / 512, 256>>>(row, col);

    // D: attention + gather
    attn_gather<<<1024 + NN_ / 8, 256, AT_SMEM_BYTES>>>(qkvbf_p, attnbf_p, x, b_conv);

    // E: h1-stats blocks (y<128, run first) + out_proj GEMM (+h2 stats)
    gemm_mma<5, 2><<<dim3(2, 384), 256, GS3>>>(attnbf_p, opw_p, nullptr, out_proj_b, x,
                                               nullptr, h2bf_p, nullptr, sum_p + CC_, sq_p + CC_, CC_, CC_);
    // F: combine
    combine_kernel<<<NN_ * CC_ / 2048, 256>>>(bn1_g, bn1_b, bn2_g, bn2_b);
    // G: ffn1
    gemm_mma<2, 0><<<dim3(4, 256), 256, GS3>>>(outbf_p, W1T_p, nullptr, mlp_b1, nullptr,
                                               nullptr, ff1bf_p, nullptr, nullptr, nullptr, 2 * CC_, CC_);
    // H: ffn2 (bf16 resid, stats + per-graph max/min; no out3 store)
    gemm_mma<6, 1><<<dim3(2, 256), 256, GS3>>>(ff1bf_p, W2T_p, nullptr, mlp_b2, nullptr,
                                               nullptr, nullptr, outbf_p, sum_p + 2 * CC_, sq_p + 2 * CC_, CC_, 2 * CC_);
    // I: pool + head
    pool_head_kernel<<<BB_, CC_>>>(bn3_g, bn3_b, fc_w, fc_b, out);
}